// round 8
// baseline (speedup 1.0000x reference)
#include <cuda_runtime.h>
#include <stdint.h>

// ---------------- problem constants ----------------
#define N_PATCH   40000
#define GRP       4
#define DIM       400          // 16*5*5
#define KC        64           // clusters
#define EPOCHS    10
#define ROWSTRIDE 1600         // GRP*DIM floats per patch row
#define KPAD      448          // DIM padded to 14 chunks of 32
#define CHUNK     32
#define NCHUNK    14
#define TM        128          // patches per tile

// smem float offsets (assign kernel)
#define AH_OFF 0               // 128 x 36 each
#define AM_OFF 4608
#define AL_OFF 9216
#define BH_OFF 13824           // 64 x 36 each
#define BM_OFF 16128
#define BL_OFF 18432
#define C2_OFF 20736           // 64 floats
#define ASSIGN_SMEM ((20736 + 64) * 4)   // 83,200 B -> 2 CTAs/SM

// sum-kernel partition
#define SUM_CTAS 74
#define PPC      541           // ceil(40000/74)
#define UB       16            // patch unroll

// ---------------- device state ----------------
__device__ float g_centroids[GRP * KC * DIM];
__device__ float g_c2[GRP * KC];
__device__ int   g_labels[GRP * N_PATCH];
__device__ float g_sums[GRP * KC * DIM];
__device__ float g_counts[GRP * KC];
// centroid tf32 3-way split planes (h, m, l), zero-padded K to 448
__device__ float g_cbh[GRP][KC][KPAD];
__device__ float g_cbm[GRP][KC][KPAD];
__device__ float g_cbl[GRP][KC][KPAD];

// ---------------- exact split via bit masking (cvt-proof) ----------------
// tf32 storage = fp32 with low 13 mantissa bits zero. Truncation split:
// h = top bits (exact tf32), r1 = x-h exact, m = top of r1, l = r1-m exact.
// x == h + m + l exactly; dropped cross terms in 6-term MMA < 2^-33 relative.
__device__ __forceinline__ float trunc_tf32(float x) {
    return __uint_as_float(__float_as_uint(x) & 0xFFFFE000u);
}
__device__ __forceinline__ void split3(float x, float& h, float& m, float& l) {
    h = trunc_tf32(x);
    float r1 = x - h;              // exact (Sterbenz)
    m = trunc_tf32(r1);
    l = r1 - m;                    // exact
}
__device__ __forceinline__ void mma_tf32(float* c, const uint32_t* a,
                                         uint32_t b0, uint32_t b1) {
    asm volatile(
        "mma.sync.aligned.m16n8k8.row.col.f32.tf32.tf32.f32 "
        "{%0,%1,%2,%3}, {%4,%5,%6,%7}, {%8,%9}, {%0,%1,%2,%3};"
        : "+f"(c[0]), "+f"(c[1]), "+f"(c[2]), "+f"(c[3])
        : "r"(a[0]), "r"(a[1]), "r"(a[2]), "r"(a[3]), "r"(b0), "r"(b1));
}

// ---------------- small kernels ----------------
__global__ void copy_init_kernel(const float* __restrict__ cin) {
    int i = blockIdx.x * blockDim.x + threadIdx.x;
    if (i < GRP * KC * DIM) g_centroids[i] = cin[i];
}

// epoch-0 prep: c2 = 0.5*||c||^2, zero sums+counts, emit split planes
__global__ void prep_kernel() {
    int b = blockIdx.x;                 // g*KC + k
    int g = b / KC, k = b % KC;
    float s = 0.f;
    for (int d = threadIdx.x; d < KPAD; d += 128) {
        float v = 0.f;
        if (d < DIM) {
            v = g_centroids[b * DIM + d];
            s += v * v;
            g_sums[b * DIM + d] = 0.f;
        }
        float h, m, l; split3(v, h, m, l);
        g_cbh[g][k][d] = h; g_cbm[g][k][d] = m; g_cbl[g][k][d] = l;
    }
#pragma unroll
    for (int o = 16; o; o >>= 1) s += __shfl_down_sync(0xffffffffu, s, o);
    __shared__ float ws[4];
    if ((threadIdx.x & 31) == 0) ws[threadIdx.x >> 5] = s;
    __syncthreads();
    if (threadIdx.x == 0) {
        g_c2[b] = 0.5f * (ws[0] + ws[1] + ws[2] + ws[3]);
        g_counts[b] = 0.f;
    }
}

// ---------------- 6-term TF32 tensor assign (exact fp32 emulation) ----------
// S[128 patch][64 clu] = P.C^T via mma.sync m16n8k8 tf32; terms hh,hm,mh,hl,lh,mm.
// Fused argmax -> labels (first-max ties).
__global__ void __launch_bounds__(256, 2) assign_kernel(const float* __restrict__ patches) {
    extern __shared__ float sm[];
    float* AH = sm + AH_OFF;    // [128][36]
    float* AM = sm + AM_OFF;
    float* AL = sm + AL_OFF;
    float* BH = sm + BH_OFF;    // [64][36]
    float* BM = sm + BM_OFF;
    float* BL = sm + BL_OFF;
    float* c2s = sm + C2_OFF;

    const int tid = threadIdx.x;
    const int wid = tid >> 5, lane = tid & 31;
    const int tg = lane >> 2, tq = lane & 3;     // groupID, threadID_in_group
    const int g = blockIdx.y;
    const int row0 = blockIdx.x * TM;
    const int r0 = wid * 16;

    if (tid < KC) c2s[tid] = g_c2[g * KC + tid];

    float acc[8][4];
#pragma unroll
    for (int j = 0; j < 8; j++)
#pragma unroll
        for (int q = 0; q < 4; q++) acc[j][q] = 0.f;

    const float* abase = patches + (size_t)row0 * ROWSTRIDE + g * DIM;

    for (int kc = 0; kc < NCHUNK; kc++) {
        const int kk = kc * CHUNK;
        // stage A: 128 rows x 32 cols fp32 -> h/m/l planes (stride 36)
#pragma unroll
        for (int l4 = 0; l4 < 4; l4++) {
            int idx = tid + l4 * 256;            // 0..1023
            int r = idx >> 3, c4 = idx & 7;
            int n = row0 + r, col = kk + c4 * 4;
            float4 v = make_float4(0.f, 0.f, 0.f, 0.f);
            if (n < N_PATCH && col < DIM)
                v = *(const float4*)(abase + (size_t)r * ROWSTRIDE + col);
            float4 h, m, l;
            split3(v.x, h.x, m.x, l.x); split3(v.y, h.y, m.y, l.y);
            split3(v.z, h.z, m.z, l.z); split3(v.w, h.w, m.w, l.w);
            *(float4*)&AH[r * 36 + c4 * 4] = h;
            *(float4*)&AM[r * 36 + c4 * 4] = m;
            *(float4*)&AL[r * 36 + c4 * 4] = l;
        }
        // stage B: 64 rows x 32 cols, precomputed split planes
#pragma unroll
        for (int l4 = 0; l4 < 2; l4++) {
            int idx = tid + l4 * 256;            // 0..511
            int r = idx >> 3, c4 = idx & 7;
            *(float4*)&BH[r * 36 + c4 * 4] = *(const float4*)&g_cbh[g][r][kk + c4 * 4];
            *(float4*)&BM[r * 36 + c4 * 4] = *(const float4*)&g_cbm[g][r][kk + c4 * 4];
            *(float4*)&BL[r * 36 + c4 * 4] = *(const float4*)&g_cbl[g][r][kk + c4 * 4];
        }
        __syncthreads();

#pragma unroll
        for (int k8 = 0; k8 < CHUNK / 8; k8++) {
            const int k = k8 * 8 + tq;
            const int ra = r0 + tg;
            uint32_t ah[4], am[4], al[4];
#define LDA(dst, P) \
            dst[0] = __float_as_uint(P[ra * 36 + k]); \
            dst[1] = __float_as_uint(P[(ra + 8) * 36 + k]); \
            dst[2] = __float_as_uint(P[ra * 36 + k + 4]); \
            dst[3] = __float_as_uint(P[(ra + 8) * 36 + k + 4]);
            LDA(ah, AH) LDA(am, AM) LDA(al, AL)
#undef LDA
#pragma unroll
            for (int j = 0; j < 8; j++) {
                const int n = j * 8 + tg;
                uint32_t bh0 = __float_as_uint(BH[n * 36 + k]);
                uint32_t bh1 = __float_as_uint(BH[n * 36 + k + 4]);
                uint32_t bm0 = __float_as_uint(BM[n * 36 + k]);
                uint32_t bm1 = __float_as_uint(BM[n * 36 + k + 4]);
                uint32_t bl0 = __float_as_uint(BL[n * 36 + k]);
                uint32_t bl1 = __float_as_uint(BL[n * 36 + k + 4]);
                mma_tf32(acc[j], al, bh0, bh1);   // lh   (small terms first)
                mma_tf32(acc[j], ah, bl0, bl1);   // hl
                mma_tf32(acc[j], am, bm0, bm1);   // mm
                mma_tf32(acc[j], am, bh0, bh1);   // mh
                mma_tf32(acc[j], ah, bm0, bm1);   // hm
                mma_tf32(acc[j], ah, bh0, bh1);   // hh
            }
        }
        __syncthreads();
    }

    // epilogue: scatter fragments to Cs[128][65] (reuses A region), argmax
    float* Cs = sm;
#pragma unroll
    for (int j = 0; j < 8; j++) {
        int c0 = j * 8 + 2 * tq;
        Cs[(r0 + tg) * 65 + c0]     = acc[j][0];
        Cs[(r0 + tg) * 65 + c0 + 1] = acc[j][1];
        Cs[(r0 + tg + 8) * 65 + c0]     = acc[j][2];
        Cs[(r0 + tg + 8) * 65 + c0 + 1] = acc[j][3];
    }
    __syncthreads();

    if (tid < TM) {
        int n = row0 + tid;
        if (n < N_PATCH) {
            const float* row = &Cs[tid * 65];
            float best = row[0] - c2s[0];
            int bi = 0;
#pragma unroll
            for (int k2 = 1; k2 < KC; k2++) {
                float v = row[k2] - c2s[k2];
                if (v > best) { best = v; bi = k2; }
            }
            g_labels[g * N_PATCH + n] = bi;
        }
    }
}

// ---------------- sum kernel (proven) ----------------
__global__ void sum_kernel(const float* __restrict__ patches) {
    extern __shared__ float ssum[];                 // KC*DIM sums + KC counts
    float* acc = ssum;
    float* cnt = ssum + KC * DIM;
    const int g   = blockIdx.y;
    const int s   = blockIdx.x;
    const int tid = threadIdx.x;

    for (int i = tid; i < KC * DIM; i += 256) acc[i] = 0.f;
    if (tid < KC) cnt[tid] = 0.f;
    __syncthreads();

    const int start = s * PPC;
    const int end   = min(start + PPC, N_PATCH);
    const int* lbl  = &g_labels[g * N_PATCH];

    for (int nb = start; nb < end; nb += UB) {
        int nu = min(UB, end - nb);
        int   l[UB];
        float v0[UB], v1[UB];
#pragma unroll
        for (int u = 0; u < UB; u++) {
            bool ok = (u < nu);
            int nn = ok ? (nb + u) : start;
            l[u] = lbl[nn];
            const float* p = &patches[(size_t)nn * ROWSTRIDE + g * DIM];
            v0[u] = ok ? p[tid] : 0.f;
            v1[u] = (ok && tid < DIM - 256) ? p[256 + tid] : 0.f;
        }
#pragma unroll
        for (int u = 0; u < UB; u++) {
            if (u < nu) {
                acc[l[u] * DIM + tid] += v0[u];
                if (tid < DIM - 256) acc[l[u] * DIM + 256 + tid] += v1[u];
                if (tid == 0) cnt[l[u]] += 1.f;
            }
        }
    }
    __syncthreads();

    for (int i = tid; i < KC * DIM; i += 256)
        atomicAdd(&g_sums[(size_t)g * KC * DIM + i], acc[i]);
    if (tid < KC) atomicAdd(&g_counts[g * KC + tid], cnt[tid]);
}

// ---------------- finalize (+ prep next epoch + split planes) -------------
__global__ void finalize_kernel(float* out) {
    int b = blockIdx.x;            // g*KC + k
    int g = b / KC, k = b % KC;
    __shared__ float denom_s;
    __shared__ int   bad_s;
    __shared__ float ws[4];
    if (threadIdx.x == 0) {
        bool bad = false;
        for (int gg = 0; gg < GRP; gg++)
            if (g_counts[gg * KC + k] == 0.f) bad = true;
        float c = g_counts[b];
        denom_s = (c == 0.f) ? 1.f : c;
        bad_s = bad ? 1 : 0;
    }
    __syncthreads();
    float denom = denom_s;
    int bad = bad_s;
    float s = 0.f;
    for (int d = threadIdx.x; d < KPAD; d += 128) {
        float v = 0.f;
        if (d < DIM) {
            v = bad ? 0.f : (g_sums[b * DIM + d] / denom);
            g_centroids[b * DIM + d] = v;
            if (out) out[b * DIM + d] = v;
            s += v * v;
            g_sums[b * DIM + d] = 0.f;             // prep next epoch
        }
        float h, m, l; split3(v, h, m, l);
        g_cbh[g][k][d] = h; g_cbm[g][k][d] = m; g_cbl[g][k][d] = l;
    }
#pragma unroll
    for (int o = 16; o; o >>= 1) s += __shfl_down_sync(0xffffffffu, s, o);
    if ((threadIdx.x & 31) == 0) ws[threadIdx.x >> 5] = s;
    __syncthreads();
    if (threadIdx.x == 0) {
        g_c2[b] = 0.5f * (ws[0] + ws[1] + ws[2] + ws[3]);
        g_counts[b] = 0.f;                         // prep next epoch
    }
}

// ---------------- launch ----------------
extern "C" void kernel_launch(void* const* d_in, const int* in_sizes, int n_in,
                              void* d_out, int out_size) {
    const float* patches = (const float*)d_in[0];
    const float* cinit   = (const float*)d_in[1];
    float* out = (float*)d_out;

    const int sum_smem = (KC * DIM + KC) * (int)sizeof(float);   // 102,656 B
    cudaFuncSetAttribute(sum_kernel, cudaFuncAttributeMaxDynamicSharedMemorySize, sum_smem);
    cudaFuncSetAttribute(assign_kernel, cudaFuncAttributeMaxDynamicSharedMemorySize, ASSIGN_SMEM);

    copy_init_kernel<<<(GRP * KC * DIM + 255) / 256, 256>>>(cinit);
    prep_kernel<<<GRP * KC, 128>>>();

    for (int e = 0; e < EPOCHS; e++) {
        assign_kernel<<<dim3((N_PATCH + TM - 1) / TM, GRP), 256, ASSIGN_SMEM>>>(patches);
        sum_kernel<<<dim3(SUM_CTAS, GRP), 256, sum_smem>>>(patches);
        finalize_kernel<<<GRP * KC, 128>>>(e == EPOCHS - 1 ? out : nullptr);
    }
}

// round 9
// speedup vs baseline: 1.2145x; 1.2145x over previous
#include <cuda_runtime.h>
#include <stdint.h>

// ---------------- problem constants ----------------
#define N_PATCH   40000
#define GRP       4
#define DIM       400          // 16*5*5
#define KC        64           // clusters
#define EPOCHS    10
#define ROWSTRIDE 1600         // GRP*DIM floats per patch row
#define TM        128          // patches per tile
#define DK        40           // k-chunk (400 = 10*40)
#define NCH       10
#define TILES_G   313          // ceil(40000/128)
#define CTAS_X    105          // 105*3 >= 313
#define TPC       3            // tiles per CTA

// fused-kernel smem layout (floats)
#define ASTR   129             // A k-major stride in float2
#define BSTR   65
#define STG_F  8320            // staging/Cs union: max(7760, 128*65)
#define ACC_F  STG_F           // accumulator offset
#define CNT_F  (ACC_F + KC*DIM)        // 33920
#define LBL_F  (CNT_F + KC)            // 33984 (ints)
#define C2_F   (LBL_F + TM)            // 34112
#define FUSED_F (C2_F + KC)            // 34176 floats
#define FUSED_SMEM (FUSED_F * 4)       // 136,704 B -> 1 CTA/SM

// ---------------- device state ----------------
__device__ float g_centroids[GRP * KC * DIM];
__device__ float g_c2[GRP * KC];
__device__ __align__(16) float g_sums[GRP * KC * DIM];
__device__ float g_counts[GRP * KC];

// ---------------- packed fp32x2 helpers ----------------
__device__ __forceinline__ void ffma2(unsigned long long& d,
                                      unsigned long long a,
                                      unsigned long long b) {
    asm("fma.rn.f32x2 %0, %1, %2, %0;" : "+l"(d) : "l"(a), "l"(b));
}
__device__ __forceinline__ float unpack_sum(unsigned long long v) {
    float lo, hi;
    asm("mov.b64 {%0, %1}, %2;" : "=f"(lo), "=f"(hi) : "l"(v));
    return lo + hi;
}

// ---------------- small kernels ----------------
__global__ void copy_init_kernel(const float* __restrict__ cin) {
    int i = blockIdx.x * blockDim.x + threadIdx.x;
    if (i < GRP * KC * DIM) g_centroids[i] = cin[i];
}

// epoch-0 prep: c2 = 0.5*||c||^2, zero sums + counts
__global__ void prep_kernel() {
    int b = blockIdx.x;                 // g*KC + k
    const float* c = &g_centroids[b * DIM];
    float s = 0.f;
    for (int d = threadIdx.x; d < DIM; d += 128) {
        float v = c[d];
        s += v * v;
        g_sums[b * DIM + d] = 0.f;
    }
#pragma unroll
    for (int o = 16; o; o >>= 1) s += __shfl_down_sync(0xffffffffu, s, o);
    __shared__ float ws[4];
    if ((threadIdx.x & 31) == 0) ws[threadIdx.x >> 5] = s;
    __syncthreads();
    if (threadIdx.x == 0) {
        g_c2[b] = 0.5f * (ws[0] + ws[1] + ws[2] + ws[3]);
        g_counts[b] = 0.f;
    }
}

// ---------------- fused assign + sum ----------------
// Per tile: FFMA2 scores (128x64, K=400) -> argmax -> labels in smem ->
// re-read tile rows (L2-hot) into per-CTA KC*DIM smem accumulator.
// One red.global flush per CTA.
__global__ void __launch_bounds__(256, 1) fused_kernel(const float* __restrict__ patches) {
    extern __shared__ float sm[];
    float2* As2 = (float2*)sm;                    // [20][ASTR]
    float2* Bs2 = (float2*)(sm + 2 * 20 * ASTR);  // [20][BSTR]
    float*  acc = sm + ACC_F;                     // [KC*DIM]
    float*  cnt = sm + CNT_F;                     // [KC]
    int*    lbl = (int*)(sm + LBL_F);             // [TM]
    float*  c2s = sm + C2_F;                      // [KC]

    const int tid = threadIdx.x;
    const int tx  = tid & 15;
    const int ty  = tid >> 4;
    const int g   = blockIdx.y;

    // zero accumulator + counts, load c2
    for (int i = tid; i < KC * DIM; i += 256) acc[i] = 0.f;
    if (tid < KC) { cnt[tid] = 0.f; c2s[tid] = g_c2[g * KC + tid]; }
    __syncthreads();

    const float* cbase = &g_centroids[g * KC * DIM];

    for (int t = 0; t < TPC; t++) {
        const int tile = blockIdx.x * TPC + t;
        if (tile >= TILES_G) break;
        const int row0 = tile * TM;
        const int nvalid = min(TM, N_PATCH - row0);
        const float* abase = patches + (size_t)row0 * ROWSTRIDE + g * DIM;

        unsigned long long accr[8][4];
#pragma unroll
        for (int i = 0; i < 8; i++)
#pragma unroll
            for (int j = 0; j < 4; j++) accr[i][j] = 0ULL;

        // prefetch chunk 0 of A into registers
        float4 apf[5];
#pragma unroll
        for (int l = 0; l < 5; l++) {
            int idx = tid + l * 256;
            int r = idx / 10, c = idx % 10;
            apf[l] = make_float4(0.f, 0.f, 0.f, 0.f);
            if (r < nvalid)
                apf[l] = *(const float4*)(abase + (size_t)r * ROWSTRIDE + c * 4);
        }

        for (int kc = 0; kc < NCH; kc++) {
            const int kk = kc * DK;
            __syncthreads();    // previous chunk consumed
            // store prefetched A (k-major float2 pairs)
#pragma unroll
            for (int l = 0; l < 5; l++) {
                int idx = tid + l * 256;
                int r = idx / 10, c = idx % 10;
                As2[(2 * c + 0) * ASTR + r] = make_float2(apf[l].x, apf[l].y);
                As2[(2 * c + 1) * ASTR + r] = make_float2(apf[l].z, apf[l].w);
            }
            // stage B chunk (centroids, L2-hot)
#pragma unroll
            for (int l = 0; l < 3; l++) {
                int idx = tid + l * 256;
                if (idx < 640) {
                    int r = idx / 10, c = idx % 10;
                    float4 v = *(const float4*)&cbase[r * DIM + kk + c * 4];
                    Bs2[(2 * c + 0) * BSTR + r] = make_float2(v.x, v.y);
                    Bs2[(2 * c + 1) * BSTR + r] = make_float2(v.z, v.w);
                }
            }
            __syncthreads();
            // prefetch next A chunk (hidden under FMA below)
            if (kc + 1 < NCH) {
                const int kn = kk + DK;
#pragma unroll
                for (int l = 0; l < 5; l++) {
                    int idx = tid + l * 256;
                    int r = idx / 10, c = idx % 10;
                    apf[l] = make_float4(0.f, 0.f, 0.f, 0.f);
                    if (r < nvalid)
                        apf[l] = *(const float4*)(abase + (size_t)r * ROWSTRIDE + kn + c * 4);
                }
            }
            // FFMA2 inner loop on current chunk
#pragma unroll
            for (int k2 = 0; k2 < DK / 2; k2++) {
                unsigned long long a2[8], b2[4];
#pragma unroll
                for (int i = 0; i < 8; i++)
                    a2[i] = *(const unsigned long long*)&As2[k2 * ASTR + ty + 16 * i];
#pragma unroll
                for (int j = 0; j < 4; j++)
                    b2[j] = *(const unsigned long long*)&Bs2[k2 * BSTR + tx + 16 * j];
#pragma unroll
                for (int i = 0; i < 8; i++)
#pragma unroll
                    for (int j = 0; j < 4; j++)
                        ffma2(accr[i][j], a2[i], b2[j]);
            }
        }
        __syncthreads();

        // epilogue: scores - c2 into Cs[128][65] (reuses staging region)
        float* Cs = sm;
#pragma unroll
        for (int i = 0; i < 8; i++)
#pragma unroll
            for (int j = 0; j < 4; j++)
                Cs[(ty + 16 * i) * 65 + (tx + 16 * j)] =
                    unpack_sum(accr[i][j]) - c2s[tx + 16 * j];
        __syncthreads();

        // argmax (first-max tie rule), label -> smem
        if (tid < TM && tid < nvalid) {
            const float* row = &Cs[tid * 65];
            float best = row[0];
            int bi = 0;
#pragma unroll
            for (int k2 = 1; k2 < KC; k2++) {
                float v = row[k2];
                if (v > best) { best = v; bi = k2; }
            }
            lbl[tid] = bi;
        }
        __syncthreads();

        // accumulate: re-read tile rows (L2-hot), add into smem accumulator
        for (int pb = 0; pb < nvalid; pb += 8) {
            int nu = min(8, nvalid - pb);
            int   l[8];
            float v0[8], v1[8];
#pragma unroll
            for (int u = 0; u < 8; u++) {
                bool ok = (u < nu);
                int pp = ok ? (pb + u) : 0;
                l[u] = lbl[pp];
                const float* p = abase + (size_t)pp * ROWSTRIDE;
                v0[u] = ok ? p[tid] : 0.f;
                v1[u] = (ok && tid < DIM - 256) ? p[256 + tid] : 0.f;
            }
#pragma unroll
            for (int u = 0; u < 8; u++) {
                if (u < nu) {
                    acc[l[u] * DIM + tid] += v0[u];
                    if (tid < DIM - 256) acc[l[u] * DIM + 256 + tid] += v1[u];
                }
            }
        }
        if (tid < nvalid) atomicAdd(&cnt[lbl[tid]], 1.f);
        __syncthreads();
    }

    // flush accumulator (vector red.global) + counts
    for (int i = tid * 4; i < KC * DIM; i += 1024) {
        float4 v = *(const float4*)&acc[i];
        float* dst = &g_sums[(size_t)g * KC * DIM + i];
        asm volatile("red.global.add.v4.f32 [%0], {%1, %2, %3, %4};"
                     :: "l"(dst), "f"(v.x), "f"(v.y), "f"(v.z), "f"(v.w)
                     : "memory");
    }
    if (tid < KC) atomicAdd(&g_counts[g * KC + tid], cnt[tid]);
}

// ---------------- finalize (+ fused prep for next epoch) ----------------
__global__ void finalize_kernel(float* out) {
    int b = blockIdx.x;            // g*KC + k
    int k = b % KC;
    __shared__ float denom_s;
    __shared__ int   bad_s;
    __shared__ float ws[4];
    if (threadIdx.x == 0) {
        bool bad = false;
        for (int gg = 0; gg < GRP; gg++)
            if (g_counts[gg * KC + k] == 0.f) bad = true;
        float c = g_counts[b];
        denom_s = (c == 0.f) ? 1.f : c;
        bad_s = bad ? 1 : 0;
    }
    __syncthreads();
    float denom = denom_s;
    int bad = bad_s;
    float s = 0.f;
    for (int d = threadIdx.x; d < DIM; d += 128) {
        float v = bad ? 0.f : (g_sums[b * DIM + d] / denom);
        g_centroids[b * DIM + d] = v;
        if (out) out[b * DIM + d] = v;
        s += v * v;
        g_sums[b * DIM + d] = 0.f;                 // prep next epoch
    }
#pragma unroll
    for (int o = 16; o; o >>= 1) s += __shfl_down_sync(0xffffffffu, s, o);
    if ((threadIdx.x & 31) == 0) ws[threadIdx.x >> 5] = s;
    __syncthreads();
    if (threadIdx.x == 0) {
        g_c2[b] = 0.5f * (ws[0] + ws[1] + ws[2] + ws[3]);
        g_counts[b] = 0.f;                         // prep next epoch
    }
}

// ---------------- launch ----------------
extern "C" void kernel_launch(void* const* d_in, const int* in_sizes, int n_in,
                              void* d_out, int out_size) {
    const float* patches = (const float*)d_in[0];
    const float* cinit   = (const float*)d_in[1];
    float* out = (float*)d_out;

    cudaFuncSetAttribute(fused_kernel, cudaFuncAttributeMaxDynamicSharedMemorySize, FUSED_SMEM);

    copy_init_kernel<<<(GRP * KC * DIM + 255) / 256, 256>>>(cinit);
    prep_kernel<<<GRP * KC, 128>>>();

    for (int e = 0; e < EPOCHS; e++) {
        fused_kernel<<<dim3(CTAS_X, GRP), 256, FUSED_SMEM>>>(patches);
        finalize_kernel<<<GRP * KC, 128>>>(e == EPOCHS - 1 ? out : nullptr);
    }
}

// round 10
// speedup vs baseline: 1.5014x; 1.2363x over previous
#include <cuda_runtime.h>
#include <stdint.h>

// ---------------- problem constants ----------------
#define N_PATCH   40000
#define GRP       4
#define DIM       400          // 16*5*5
#define KC        64
#define EPOCHS    10
#define ROWSTRIDE 1600         // GRP*DIM floats per patch row
#define TM        128          // patches per tile (MMA M)
#define KPADP     208          // K padded to 416 = 208 bf16-pairs
#define NCH       13           // chunks of 32 k (16 pairs)
#define TILES_G   313
#define CTAS_X    105
#define TPC       3

// fused-kernel smem layout
#define APW    20              // pair-slots per row (16 + 4 pad) in uint32
#define APL2   (128*APW)       // 2560 u32 per A plane
#define BPL2   (64*APW)        // 1280 u32 per B plane
#define STG_F  (3*APL2 + 3*BPL2)       // 11520 (>= Cs 128*65=8320)
#define ACC_F  STG_F
#define CNT_F  (ACC_F + KC*DIM)
#define LBL_F  (CNT_F + KC)
#define C2_F   (LBL_F + TM)
#define FUSED_F (C2_F + KC)            // 37376 floats
#define FUSED_SMEM (FUSED_F * 4)       // 149,504 B -> 1 CTA/SM

// ---------------- device state ----------------
__device__ float g_centroids[GRP * KC * DIM];
__device__ float g_c2[GRP * KC];
__device__ __align__(16) float g_sums[GRP * KC * DIM];
__device__ float g_counts[GRP * KC];
// centroid bf16-pair-packed planes (h,m,l)
__device__ __align__(16) uint32_t g_cbp[GRP][3][KC][KPADP];

// ---------------- bf16 split helpers (exact bit-mask, cvt-proof) ----------
// h = top 16 bits (exact bf16 trunc); r1 = x-h exact; m = trunc(r1);
// r2 = r1-m exact; l = trunc(r2). x = h+m+l + O(2^-24 x).
__device__ __forceinline__ void split3b(float x, uint32_t& h, uint32_t& m, uint32_t& l) {
    uint32_t xb = __float_as_uint(x);
    h = xb & 0xFFFF0000u;
    float r1 = x - __uint_as_float(h);
    m = __float_as_uint(r1) & 0xFFFF0000u;
    float r2 = r1 - __uint_as_float(m);
    l = __float_as_uint(r2) & 0xFFFF0000u;
}
// pack bf16(a),bf16(b) -> (b_hi16 | a_hi16>>16)
__device__ __forceinline__ uint32_t packh(uint32_t a, uint32_t b) {
    return __byte_perm(a, b, 0x7632);
}
__device__ __forceinline__ void mma_bf16(float* c, const uint32_t* a,
                                         uint32_t b0, uint32_t b1) {
    asm volatile(
        "mma.sync.aligned.m16n8k16.row.col.f32.bf16.bf16.f32 "
        "{%0,%1,%2,%3}, {%4,%5,%6,%7}, {%8,%9}, {%0,%1,%2,%3};"
        : "+f"(c[0]), "+f"(c[1]), "+f"(c[2]), "+f"(c[3])
        : "r"(a[0]), "r"(a[1]), "r"(a[2]), "r"(a[3]), "r"(b0), "r"(b1));
}

// ---------------- small kernels ----------------
__global__ void copy_init_kernel(const float* __restrict__ cin) {
    int i = blockIdx.x * blockDim.x + threadIdx.x;
    if (i < GRP * KC * DIM) g_centroids[i] = cin[i];
}

// emit packed planes + c2 + zero sums/counts for one (g,k)
__device__ __forceinline__ void emit_planes(int g, int k, int b, const float* src,
                                            float denom, int bad, float* out,
                                            bool writeback) {
    float s = 0.f;
    for (int pp = threadIdx.x; pp < KPADP; pp += 128) {
        int k0 = 2 * pp;
        float v0 = 0.f, v1 = 0.f;
        if (k0 < DIM) {
            v0 = bad ? 0.f : src[k0] / denom;
            if (writeback) {
                g_centroids[b * DIM + k0] = v0;
                if (out) out[b * DIM + k0] = v0;
                g_sums[b * DIM + k0] = 0.f;
            }
            s += v0 * v0;
        }
        if (k0 + 1 < DIM) {
            v1 = bad ? 0.f : src[k0 + 1] / denom;
            if (writeback) {
                g_centroids[b * DIM + k0 + 1] = v1;
                if (out) out[b * DIM + k0 + 1] = v1;
                g_sums[b * DIM + k0 + 1] = 0.f;
            }
            s += v1 * v1;
        }
        uint32_t h0, m0, l0, h1, m1, l1;
        split3b(v0, h0, m0, l0);
        split3b(v1, h1, m1, l1);
        g_cbp[g][0][k][pp] = packh(h0, h1);
        g_cbp[g][1][k][pp] = packh(m0, m1);
        g_cbp[g][2][k][pp] = packh(l0, l1);
    }
#pragma unroll
    for (int o = 16; o; o >>= 1) s += __shfl_down_sync(0xffffffffu, s, o);
    __shared__ float ws[4];
    if ((threadIdx.x & 31) == 0) ws[threadIdx.x >> 5] = s;
    __syncthreads();
    if (threadIdx.x == 0) {
        g_c2[b] = 0.5f * (ws[0] + ws[1] + ws[2] + ws[3]);
        g_counts[b] = 0.f;
    }
}

__global__ void prep_kernel() {
    int b = blockIdx.x, g = b / KC, k = b % KC;
    // initial centroids already in g_centroids; zero sums here
    for (int d = threadIdx.x; d < DIM; d += 128) g_sums[b * DIM + d] = 0.f;
    emit_planes(g, k, b, &g_centroids[b * DIM], 1.f, 0, nullptr, false);
}

__global__ void finalize_kernel(float* out) {
    int b = blockIdx.x, g = b / KC, k = b % KC;
    __shared__ float denom_s;
    __shared__ int bad_s;
    if (threadIdx.x == 0) {
        bool bad = false;
        for (int gg = 0; gg < GRP; gg++)
            if (g_counts[gg * KC + k] == 0.f) bad = true;
        float c = g_counts[b];
        denom_s = (c == 0.f) ? 1.f : c;
        bad_s = bad ? 1 : 0;
    }
    __syncthreads();
    emit_planes(g, k, b, &g_sums[b * DIM], denom_s, bad_s, out, true);
}

// ---------------- fused assign(bf16 6-term MMA) + sum ----------------
__global__ void __launch_bounds__(256, 1) fused_kernel(const float* __restrict__ patches) {
    extern __shared__ float sm[];
    uint32_t* Apk = (uint32_t*)sm;                 // [3][128][APW]
    uint32_t* Bpk = (uint32_t*)sm + 3 * APL2;      // [3][64][APW]
    float* acc = sm + ACC_F;
    float* cnt = sm + CNT_F;
    int*   lbl = (int*)(sm + LBL_F);
    float* c2s = sm + C2_F;

    const int tid = threadIdx.x;
    const int w = tid >> 5, lane = tid & 31;
    const int tg = lane >> 2, tq = lane & 3;
    const int g = blockIdx.y;

    for (int i = tid; i < KC * DIM; i += 256) acc[i] = 0.f;
    if (tid < KC) { cnt[tid] = 0.f; c2s[tid] = g_c2[g * KC + tid]; }
    __syncthreads();

    for (int t = 0; t < TPC; t++) {
        const int tile = blockIdx.x * TPC + t;
        if (tile >= TILES_G) break;
        const int row0 = tile * TM;
        const int nvalid = min(TM, N_PATCH - row0);
        const float* abase = patches + (size_t)row0 * ROWSTRIDE + g * DIM;

        float accr[8][4];
#pragma unroll
        for (int j = 0; j < 8; j++)
#pragma unroll
            for (int q = 0; q < 4; q++) accr[j][q] = 0.f;

        // prefetch chunk 0: 128 rows x 32 cols = 1024 float4
        float4 apf[4];
#pragma unroll
        for (int it = 0; it < 4; it++) {
            int idx = tid + it * 256;
            int r = idx >> 3, c4 = idx & 7;
            apf[it] = make_float4(0.f, 0.f, 0.f, 0.f);
            if (r < nvalid)
                apf[it] = *(const float4*)(abase + (size_t)r * ROWSTRIDE + c4 * 4);
        }

        for (int kc = 0; kc < NCH; kc++) {
            __syncthreads();
            // store prefetched A as packed bf16 pairs, 3 planes
#pragma unroll
            for (int it = 0; it < 4; it++) {
                int idx = tid + it * 256;
                int r = idx >> 3, c4 = idx & 7;
                float4 v = apf[it];
                uint32_t h0,m0,l0,h1,m1,l1,h2,m2,l2,h3,m3,l3;
                split3b(v.x, h0, m0, l0); split3b(v.y, h1, m1, l1);
                split3b(v.z, h2, m2, l2); split3b(v.w, h3, m3, l3);
                uint32_t base = r * APW + 2 * c4;
                *(uint2*)&Apk[0 * APL2 + base] = make_uint2(packh(h0, h1), packh(h2, h3));
                *(uint2*)&Apk[1 * APL2 + base] = make_uint2(packh(m0, m1), packh(m2, m3));
                *(uint2*)&Apk[2 * APL2 + base] = make_uint2(packh(l0, l1), packh(l2, l3));
            }
            // stage B planes: 3 x 64 x 16 pairs
#pragma unroll
            for (int it = 0; it < 3; it++) {
                int idx = tid + it * 256;        // 0..767
                int p = idx >> 8, e = idx & 255;
                int n = e >> 2, q = e & 3;
                uint4 v = *(const uint4*)&g_cbp[g][p][n][kc * 16 + q * 4];
                *(uint4*)&Bpk[p * BPL2 + n * APW + q * 4] = v;
            }
            __syncthreads();
            // prefetch next chunk
            if (kc + 1 < NCH) {
                const int kn = (kc + 1) * 32;
#pragma unroll
                for (int it = 0; it < 4; it++) {
                    int idx = tid + it * 256;
                    int r = idx >> 3, c4 = idx & 7;
                    int col = kn + c4 * 4;
                    apf[it] = make_float4(0.f, 0.f, 0.f, 0.f);
                    if (r < nvalid && col < DIM)
                        apf[it] = *(const float4*)(abase + (size_t)r * ROWSTRIDE + col);
                }
            }
            // 2 k16-steps per chunk
#pragma unroll
            for (int s = 0; s < 2; s++) {
                const int ar = (w * 16 + tg) * APW + 8 * s + tq;
                uint32_t ah[4], am[4], al[4];
#define LDAF(dst, P) \
                dst[0] = Apk[P * APL2 + ar]; \
                dst[1] = Apk[P * APL2 + ar + 8 * APW]; \
                dst[2] = Apk[P * APL2 + ar + 4]; \
                dst[3] = Apk[P * APL2 + ar + 8 * APW + 4];
                LDAF(ah, 0) LDAF(am, 1) LDAF(al, 2)
#undef LDAF
#pragma unroll
                for (int j = 0; j < 8; j++) {
                    const int nb = (8 * j + tg) * APW + 8 * s + tq;
                    uint32_t bh0 = Bpk[0 * BPL2 + nb], bh1 = Bpk[0 * BPL2 + nb + 4];
                    uint32_t bm0 = Bpk[1 * BPL2 + nb], bm1 = Bpk[1 * BPL2 + nb + 4];
                    uint32_t bl0 = Bpk[2 * BPL2 + nb], bl1 = Bpk[2 * BPL2 + nb + 4];
                    mma_bf16(accr[j], al, bh0, bh1);   // lh (small first)
                    mma_bf16(accr[j], ah, bl0, bl1);   // hl
                    mma_bf16(accr[j], am, bm0, bm1);   // mm
                    mma_bf16(accr[j], am, bh0, bh1);   // mh
                    mma_bf16(accr[j], ah, bm0, bm1);   // hm
                    mma_bf16(accr[j], ah, bh0, bh1);   // hh
                }
            }
        }
        __syncthreads();

        // epilogue: fragments -> Cs[128][65] (raw scores)
        float* Cs = sm;
#pragma unroll
        for (int j = 0; j < 8; j++) {
            int c0 = j * 8 + 2 * tq;
            int rr = w * 16 + tg;
            Cs[rr * 65 + c0]     = accr[j][0];
            Cs[rr * 65 + c0 + 1] = accr[j][1];
            Cs[(rr + 8) * 65 + c0]     = accr[j][2];
            Cs[(rr + 8) * 65 + c0 + 1] = accr[j][3];
        }
        __syncthreads();

        // argmax (first-max ties), labels in smem
        if (tid < TM && tid < nvalid) {
            const float* row = &Cs[tid * 65];
            float best = row[0] - c2s[0];
            int bi = 0;
#pragma unroll
            for (int k2 = 1; k2 < KC; k2++) {
                float v = row[k2] - c2s[k2];
                if (v > best) { best = v; bi = k2; }
            }
            lbl[tid] = bi;
        }
        __syncthreads();

        // accumulate: re-read tile rows (L2-hot) into smem accumulator
        for (int pb = 0; pb < nvalid; pb += 8) {
            int nu = min(8, nvalid - pb);
            int   l[8];
            float v0[8], v1[8];
#pragma unroll
            for (int u = 0; u < 8; u++) {
                bool ok = (u < nu);
                int pp = ok ? (pb + u) : 0;
                l[u] = lbl[pp];
                const float* p = abase + (size_t)pp * ROWSTRIDE;
                v0[u] = ok ? p[tid] : 0.f;
                v1[u] = (ok && tid < DIM - 256) ? p[256 + tid] : 0.f;
            }
#pragma unroll
            for (int u = 0; u < 8; u++) {
                if (u < nu) {
                    acc[l[u] * DIM + tid] += v0[u];
                    if (tid < DIM - 256) acc[l[u] * DIM + 256 + tid] += v1[u];
                }
            }
        }
        if (tid < nvalid) atomicAdd(&cnt[lbl[tid]], 1.f);
        __syncthreads();
    }

    // flush accumulator + counts
    for (int i = tid * 4; i < KC * DIM; i += 1024) {
        float4 v = *(const float4*)&acc[i];
        float* dst = &g_sums[(size_t)g * KC * DIM + i];
        asm volatile("red.global.add.v4.f32 [%0], {%1, %2, %3, %4};"
                     :: "l"(dst), "f"(v.x), "f"(v.y), "f"(v.z), "f"(v.w)
                     : "memory");
    }
    if (tid < KC) atomicAdd(&g_counts[g * KC + tid], cnt[tid]);
}

// ---------------- launch ----------------
extern "C" void kernel_launch(void* const* d_in, const int* in_sizes, int n_in,
                              void* d_out, int out_size) {
    const float* patches = (const float*)d_in[0];
    const float* cinit   = (const float*)d_in[1];
    float* out = (float*)d_out;

    cudaFuncSetAttribute(fused_kernel, cudaFuncAttributeMaxDynamicSharedMemorySize, FUSED_SMEM);

    copy_init_kernel<<<(GRP * KC * DIM + 255) / 256, 256>>>(cinit);
    prep_kernel<<<GRP * KC, 128>>>();

    for (int e = 0; e < EPOCHS; e++) {
        fused_kernel<<<dim3(CTAS_X, GRP), 256, FUSED_SMEM>>>(patches);
        finalize_kernel<<<GRP * KC, 128>>>(e == EPOCHS - 1 ? out : nullptr);
    }
}

// round 11
// speedup vs baseline: 1.5069x; 1.0036x over previous
#include <cuda_runtime.h>
#include <stdint.h>

// ---------------- problem constants ----------------
#define N_PATCH   40000
#define GRP       4
#define DIM       400          // 16*5*5
#define KC        64
#define EPOCHS    10
#define ROWSTRIDE 1600         // GRP*DIM floats per patch row
#define TM        128          // patches per tile (MMA M)
#define KPADP     208          // K padded to 416 = 208 bf16-pairs
#define NCH       13           // chunks of 32 k (16 pairs)
#define TILES_G   313
#define CTAS_X    37           // persistent: 37*4 = 148 CTAs = 1 wave
#define THREADS   512

// fused-kernel smem layout
#define APW    20              // pair-slots per row (16 + 4 pad) in uint32
#define APL2   (128*APW)       // 2560 u32 per A plane
#define BPL2   (64*APW)        // 1280 u32 per B plane
#define STG_F  (3*APL2 + 3*BPL2)       // 11520 (>= Cs 128*65=8320)
#define ACC_F  STG_F
#define CNT_F  (ACC_F + KC*DIM)
#define LBL_F  (CNT_F + KC)
#define C2_F   (LBL_F + TM)
#define FUSED_F (C2_F + KC)            // 37376 floats
#define FUSED_SMEM (FUSED_F * 4)       // 149,504 B -> 1 CTA/SM

// ---------------- device state ----------------
__device__ float g_centroids[GRP * KC * DIM];
__device__ float g_c2[GRP * KC];
__device__ __align__(16) float g_sums[GRP * KC * DIM];
__device__ float g_counts[GRP * KC];
// centroid bf16-pair-packed planes (h,m,l)
__device__ __align__(16) uint32_t g_cbp[GRP][3][KC][KPADP];

// ---------------- bf16 split helpers (exact bit-mask) ----------------
__device__ __forceinline__ void split3b(float x, uint32_t& h, uint32_t& m, uint32_t& l) {
    uint32_t xb = __float_as_uint(x);
    h = xb & 0xFFFF0000u;
    float r1 = x - __uint_as_float(h);
    m = __float_as_uint(r1) & 0xFFFF0000u;
    float r2 = r1 - __uint_as_float(m);
    l = __float_as_uint(r2) & 0xFFFF0000u;
}
__device__ __forceinline__ uint32_t packh(uint32_t a, uint32_t b) {
    return __byte_perm(a, b, 0x7632);
}
__device__ __forceinline__ void mma_bf16(float* c, const uint32_t* a,
                                         uint32_t b0, uint32_t b1) {
    asm volatile(
        "mma.sync.aligned.m16n8k16.row.col.f32.bf16.bf16.f32 "
        "{%0,%1,%2,%3}, {%4,%5,%6,%7}, {%8,%9}, {%0,%1,%2,%3};"
        : "+f"(c[0]), "+f"(c[1]), "+f"(c[2]), "+f"(c[3])
        : "r"(a[0]), "r"(a[1]), "r"(a[2]), "r"(a[3]), "r"(b0), "r"(b1));
}

// ---------------- small kernels ----------------
__global__ void copy_init_kernel(const float* __restrict__ cin) {
    int i = blockIdx.x * blockDim.x + threadIdx.x;
    if (i < GRP * KC * DIM) g_centroids[i] = cin[i];
}

// emit packed planes + c2 + zero counts for one (g,k)
__device__ __forceinline__ void emit_planes(int g, int k, int b, const float* src,
                                            float denom, int bad, float* out,
                                            bool writeback) {
    float s = 0.f;
    for (int pp = threadIdx.x; pp < KPADP; pp += 128) {
        int k0 = 2 * pp;
        float v0 = 0.f, v1 = 0.f;
        if (k0 < DIM) {
            v0 = bad ? 0.f : src[k0] / denom;
            if (writeback) {
                g_centroids[b * DIM + k0] = v0;
                if (out) out[b * DIM + k0] = v0;
                g_sums[b * DIM + k0] = 0.f;
            }
            s += v0 * v0;
        }
        if (k0 + 1 < DIM) {
            v1 = bad ? 0.f : src[k0 + 1] / denom;
            if (writeback) {
                g_centroids[b * DIM + k0 + 1] = v1;
                if (out) out[b * DIM + k0 + 1] = v1;
                g_sums[b * DIM + k0 + 1] = 0.f;
            }
            s += v1 * v1;
        }
        uint32_t h0, m0, l0, h1, m1, l1;
        split3b(v0, h0, m0, l0);
        split3b(v1, h1, m1, l1);
        g_cbp[g][0][k][pp] = packh(h0, h1);
        g_cbp[g][1][k][pp] = packh(m0, m1);
        g_cbp[g][2][k][pp] = packh(l0, l1);
    }
#pragma unroll
    for (int o = 16; o; o >>= 1) s += __shfl_down_sync(0xffffffffu, s, o);
    __shared__ float ws[4];
    if ((threadIdx.x & 31) == 0) ws[threadIdx.x >> 5] = s;
    __syncthreads();
    if (threadIdx.x == 0) {
        g_c2[b] = 0.5f * (ws[0] + ws[1] + ws[2] + ws[3]);
        g_counts[b] = 0.f;
    }
}

__global__ void prep_kernel() {
    int b = blockIdx.x, g = b / KC, k = b % KC;
    for (int d = threadIdx.x; d < DIM; d += 128) g_sums[b * DIM + d] = 0.f;
    emit_planes(g, k, b, &g_centroids[b * DIM], 1.f, 0, nullptr, false);
}

__global__ void finalize_kernel(float* out) {
    int b = blockIdx.x, g = b / KC, k = b % KC;
    __shared__ float denom_s;
    __shared__ int bad_s;
    if (threadIdx.x == 0) {
        bool bad = false;
        for (int gg = 0; gg < GRP; gg++)
            if (g_counts[gg * KC + k] == 0.f) bad = true;
        float c = g_counts[b];
        denom_s = (c == 0.f) ? 1.f : c;
        bad_s = bad ? 1 : 0;
    }
    __syncthreads();
    emit_planes(g, k, b, &g_sums[b * DIM], denom_s, bad_s, out, true);
}

// ---------------- fused assign(bf16 6-term MMA) + sum, persistent ----------
__global__ void __launch_bounds__(THREADS, 1) fused_kernel(const float* __restrict__ patches) {
    extern __shared__ float sm[];
    uint32_t* Apk = (uint32_t*)sm;                 // [3][128][APW]
    uint32_t* Bpk = (uint32_t*)sm + 3 * APL2;      // [3][64][APW]
    float* acc = sm + ACC_F;
    float* cnt = sm + CNT_F;
    int*   lbl = (int*)(sm + LBL_F);
    float* c2s = sm + C2_F;

    const int tid = threadIdx.x;
    const int w = tid >> 5, lane = tid & 31;
    const int tg = lane >> 2, tq = lane & 3;
    const int mw = w >> 1;                 // 0..7: 16-row slab
    const int nh = w & 1;                  // 0..1: 32-col half
    const int g = blockIdx.y;

    for (int i = tid; i < KC * DIM; i += THREADS) acc[i] = 0.f;
    if (tid < KC) { cnt[tid] = 0.f; c2s[tid] = g_c2[g * KC + tid]; }
    __syncthreads();

    for (int t = 0; ; t++) {
        const int tile = blockIdx.x + CTAS_X * t;
        if (tile >= TILES_G) break;
        const int row0 = tile * TM;
        const int nvalid = min(TM, N_PATCH - row0);
        const float* abase = patches + (size_t)row0 * ROWSTRIDE + g * DIM;

        float accr[4][4];
#pragma unroll
        for (int j = 0; j < 4; j++)
#pragma unroll
            for (int q = 0; q < 4; q++) accr[j][q] = 0.f;

        // prefetch chunk 0: 128 rows x 32 cols = 1024 float4
        float4 apf[2];
#pragma unroll
        for (int it = 0; it < 2; it++) {
            int idx = tid + it * THREADS;
            int r = idx >> 3, c4 = idx & 7;
            apf[it] = make_float4(0.f, 0.f, 0.f, 0.f);
            if (r < nvalid)
                apf[it] = *(const float4*)(abase + (size_t)r * ROWSTRIDE + c4 * 4);
        }

        for (int kc = 0; kc < NCH; kc++) {
            __syncthreads();
            // store prefetched A as packed bf16 pairs, 3 planes
#pragma unroll
            for (int it = 0; it < 2; it++) {
                int idx = tid + it * THREADS;
                int r = idx >> 3, c4 = idx & 7;
                float4 v = apf[it];
                uint32_t h0,m0,l0,h1,m1,l1,h2,m2,l2,h3,m3,l3;
                split3b(v.x, h0, m0, l0); split3b(v.y, h1, m1, l1);
                split3b(v.z, h2, m2, l2); split3b(v.w, h3, m3, l3);
                uint32_t base = r * APW + 2 * c4;
                *(uint2*)&Apk[0 * APL2 + base] = make_uint2(packh(h0, h1), packh(h2, h3));
                *(uint2*)&Apk[1 * APL2 + base] = make_uint2(packh(m0, m1), packh(m2, m3));
                *(uint2*)&Apk[2 * APL2 + base] = make_uint2(packh(l0, l1), packh(l2, l3));
            }
            // stage B planes: 3 x 64 x 16 pairs = 768 uint4
#pragma unroll
            for (int it = 0; it < 2; it++) {
                int idx = tid + it * THREADS;
                if (idx < 768) {
                    int p = idx >> 8, e = idx & 255;
                    int n = e >> 2, q = e & 3;
                    uint4 v = *(const uint4*)&g_cbp[g][p][n][kc * 16 + q * 4];
                    *(uint4*)&Bpk[p * BPL2 + n * APW + q * 4] = v;
                }
            }
            __syncthreads();
            // prefetch next chunk (hidden under MMA)
            if (kc + 1 < NCH) {
                const int kn = (kc + 1) * 32;
#pragma unroll
                for (int it = 0; it < 2; it++) {
                    int idx = tid + it * THREADS;
                    int r = idx >> 3, c4 = idx & 7;
                    int col = kn + c4 * 4;
                    apf[it] = make_float4(0.f, 0.f, 0.f, 0.f);
                    if (r < nvalid && col < DIM)
                        apf[it] = *(const float4*)(abase + (size_t)r * ROWSTRIDE + col);
                }
            }
            // 2 k16-steps per chunk
#pragma unroll
            for (int s = 0; s < 2; s++) {
                const int ar = (mw * 16 + tg) * APW + 8 * s + tq;
                uint32_t ah[4], am[4], al[4];
#define LDAF(dst, P) \
                dst[0] = Apk[P * APL2 + ar]; \
                dst[1] = Apk[P * APL2 + ar + 8 * APW]; \
                dst[2] = Apk[P * APL2 + ar + 4]; \
                dst[3] = Apk[P * APL2 + ar + 8 * APW + 4];
                LDAF(ah, 0) LDAF(am, 1) LDAF(al, 2)
#undef LDAF
#pragma unroll
                for (int j = 0; j < 4; j++) {
                    const int nb = (nh * 32 + 8 * j + tg) * APW + 8 * s + tq;
                    uint32_t bh0 = Bpk[0 * BPL2 + nb], bh1 = Bpk[0 * BPL2 + nb + 4];
                    uint32_t bm0 = Bpk[1 * BPL2 + nb], bm1 = Bpk[1 * BPL2 + nb + 4];
                    uint32_t bl0 = Bpk[2 * BPL2 + nb], bl1 = Bpk[2 * BPL2 + nb + 4];
                    mma_bf16(accr[j], al, bh0, bh1);   // lh (small first)
                    mma_bf16(accr[j], ah, bl0, bl1);   // hl
                    mma_bf16(accr[j], am, bm0, bm1);   // mm
                    mma_bf16(accr[j], am, bh0, bh1);   // mh
                    mma_bf16(accr[j], ah, bm0, bm1);   // hm
                    mma_bf16(accr[j], ah, bh0, bh1);   // hh
                }
            }
        }
        __syncthreads();

        // epilogue: fragments -> Cs[128][65] (raw scores)
        float* Cs = sm;
#pragma unroll
        for (int j = 0; j < 4; j++) {
            int c0 = nh * 32 + j * 8 + 2 * tq;
            int rr = mw * 16 + tg;
            Cs[rr * 65 + c0]     = accr[j][0];
            Cs[rr * 65 + c0 + 1] = accr[j][1];
            Cs[(rr + 8) * 65 + c0]     = accr[j][2];
            Cs[(rr + 8) * 65 + c0 + 1] = accr[j][3];
        }
        __syncthreads();

        // argmax (first-max ties), labels in smem
        if (tid < TM && tid < nvalid) {
            const float* row = &Cs[tid * 65];
            float best = row[0] - c2s[0];
            int bi = 0;
#pragma unroll
            for (int k2 = 1; k2 < KC; k2++) {
                float v = row[k2] - c2s[k2];
                if (v > best) { best = v; bi = k2; }
            }
            lbl[tid] = bi;
        }
        __syncthreads();

        // accumulate: re-read tile rows (L2-hot) into smem accumulator
        const bool col_ok = (tid < DIM);
        for (int pb = 0; pb < nvalid; pb += 8) {
            int nu = min(8, nvalid - pb);
            int   l[8];
            float v0[8];
#pragma unroll
            for (int u = 0; u < 8; u++) {
                bool ok = (u < nu);
                int pp = ok ? (pb + u) : 0;
                l[u] = lbl[pp];
                v0[u] = (ok && col_ok) ? abase[(size_t)pp * ROWSTRIDE + tid] : 0.f;
            }
#pragma unroll
            for (int u = 0; u < 8; u++) {
                if (u < nu && col_ok) acc[l[u] * DIM + tid] += v0[u];
            }
        }
        if (tid < nvalid) atomicAdd(&cnt[lbl[tid]], 1.f);
        __syncthreads();
    }

    // flush accumulator + counts (once per persistent CTA)
    for (int i = tid * 4; i < KC * DIM; i += THREADS * 4) {
        float4 v = *(const float4*)&acc[i];
        float* dst = &g_sums[(size_t)g * KC * DIM + i];
        asm volatile("red.global.add.v4.f32 [%0], {%1, %2, %3, %4};"
                     :: "l"(dst), "f"(v.x), "f"(v.y), "f"(v.z), "f"(v.w)
                     : "memory");
    }
    if (tid < KC) atomicAdd(&g_counts[g * KC + tid], cnt[tid]);
}

// ---------------- launch ----------------
extern "C" void kernel_launch(void* const* d_in, const int* in_sizes, int n_in,
                              void* d_out, int out_size) {
    const float* patches = (const float*)d_in[0];
    const float* cinit   = (const float*)d_in[1];
    float* out = (float*)d_out;

    cudaFuncSetAttribute(fused_kernel, cudaFuncAttributeMaxDynamicSharedMemorySize, FUSED_SMEM);

    copy_init_kernel<<<(GRP * KC * DIM + 255) / 256, 256>>>(cinit);
    prep_kernel<<<GRP * KC, 128>>>();

    for (int e = 0; e < EPOCHS; e++) {
        fused_kernel<<<dim3(CTAS_X, GRP), THREADS, FUSED_SMEM>>>(patches);
        finalize_kernel<<<GRP * KC, 128>>>(e == EPOCHS - 1 ? out : nullptr);
    }
}

// round 12
// speedup vs baseline: 1.8724x; 1.2425x over previous
#include <cuda_runtime.h>
#include <cuda_fp16.h>
#include <stdint.h>

// ---------------- problem constants ----------------
#define N_PATCH   40000
#define GRP       4
#define DIM       400          // 16*5*5
#define KC        64
#define EPOCHS    10
#define ROWSTRIDE 1600         // GRP*DIM floats per patch row
#define TM        128          // patches per tile (MMA M)
#define KPADP     208          // K padded to 416 = 208 fp16-pairs
#define NCH       13           // chunks of 32 k (16 pairs)
#define TILES_G   313
#define CTAS_X    37           // persistent: 37*4 = 148 CTAs = 1 wave
#define THREADS   512
#define LSCALE    2048.0f      // low-plane scale 2^11
#define LINV      4.8828125e-4f

// fused-kernel smem layout
#define APW    20              // pair-slots per row (16 + 4 pad) in uint32
#define APL2   (128*APW)       // 2560 u32 per A plane
#define BPL2   (64*APW)        // 1280 u32 per B plane
#define STG_F  8320            // union: 2*APL2+2*BPL2=7680 staged OR Cs 128*65
#define ACC_F  STG_F
#define CNT_F  (ACC_F + KC*DIM)
#define LBL_F  (CNT_F + KC)
#define C2_F   (LBL_F + TM)
#define FUSED_F (C2_F + KC)            // 34176 floats
#define FUSED_SMEM (FUSED_F * 4)       // 136,704 B -> 1 CTA/SM

// ---------------- device state ----------------
__device__ float g_centroids[GRP * KC * DIM];
__device__ float g_c2[GRP * KC];
__device__ __align__(16) float g_sums[GRP * KC * DIM];
__device__ float g_counts[GRP * KC];
// centroid fp16-pair-packed planes (h, l'=l*2^11)
__device__ __align__(16) uint32_t g_cbp[GRP][2][KC][KPADP];

// ---------------- fp16 split helpers ----------------
// h = rn_fp16(x); r = x-h exact; l' = rn_fp16(r*2^11) (always normal).
// x = h + l'*2^-11 + e, |e| <= 2^-22 |x|.
__device__ __forceinline__ void split2h(float x, uint32_t& h, uint32_t& l) {
    __half hh = __float2half_rn(x);
    float r = x - __half2float(hh);
    __half ll = __float2half_rn(r * LSCALE);
    h = (uint32_t)__half_as_ushort(hh);
    l = (uint32_t)__half_as_ushort(ll);
}
__device__ __forceinline__ uint32_t pack2(uint32_t a, uint32_t b) {
    return a | (b << 16);
}
__device__ __forceinline__ void mma_f16(float* c, const uint32_t* a,
                                        uint32_t b0, uint32_t b1) {
    asm volatile(
        "mma.sync.aligned.m16n8k16.row.col.f32.f16.f16.f32 "
        "{%0,%1,%2,%3}, {%4,%5,%6,%7}, {%8,%9}, {%0,%1,%2,%3};"
        : "+f"(c[0]), "+f"(c[1]), "+f"(c[2]), "+f"(c[3])
        : "r"(a[0]), "r"(a[1]), "r"(a[2]), "r"(a[3]), "r"(b0), "r"(b1));
}

// ---------------- small kernels ----------------
__global__ void copy_init_kernel(const float* __restrict__ cin) {
    int i = blockIdx.x * blockDim.x + threadIdx.x;
    if (i < GRP * KC * DIM) g_centroids[i] = cin[i];
}

// emit packed planes + c2 + zero counts for one (g,k)
__device__ __forceinline__ void emit_planes(int g, int k, int b, const float* src,
                                            float denom, int bad, float* out,
                                            bool writeback) {
    float s = 0.f;
    for (int pp = threadIdx.x; pp < KPADP; pp += 128) {
        int k0 = 2 * pp;
        float v0 = 0.f, v1 = 0.f;
        if (k0 < DIM) {
            v0 = bad ? 0.f : src[k0] / denom;
            if (writeback) {
                g_centroids[b * DIM + k0] = v0;
                if (out) out[b * DIM + k0] = v0;
                g_sums[b * DIM + k0] = 0.f;
            }
            s += v0 * v0;
        }
        if (k0 + 1 < DIM) {
            v1 = bad ? 0.f : src[k0 + 1] / denom;
            if (writeback) {
                g_centroids[b * DIM + k0 + 1] = v1;
                if (out) out[b * DIM + k0 + 1] = v1;
                g_sums[b * DIM + k0 + 1] = 0.f;
            }
            s += v1 * v1;
        }
        uint32_t h0, l0, h1, l1;
        split2h(v0, h0, l0);
        split2h(v1, h1, l1);
        g_cbp[g][0][k][pp] = pack2(h0, h1);
        g_cbp[g][1][k][pp] = pack2(l0, l1);
    }
#pragma unroll
    for (int o = 16; o; o >>= 1) s += __shfl_down_sync(0xffffffffu, s, o);
    __shared__ float ws[4];
    if ((threadIdx.x & 31) == 0) ws[threadIdx.x >> 5] = s;
    __syncthreads();
    if (threadIdx.x == 0) {
        g_c2[b] = 0.5f * (ws[0] + ws[1] + ws[2] + ws[3]);
        g_counts[b] = 0.f;
    }
}

__global__ void prep_kernel() {
    int b = blockIdx.x, g = b / KC, k = b % KC;
    for (int d = threadIdx.x; d < DIM; d += 128) g_sums[b * DIM + d] = 0.f;
    emit_planes(g, k, b, &g_centroids[b * DIM], 1.f, 0, nullptr, false);
}

__global__ void finalize_kernel(float* out) {
    int b = blockIdx.x, g = b / KC, k = b % KC;
    __shared__ float denom_s;
    __shared__ int bad_s;
    if (threadIdx.x == 0) {
        bool bad = false;
        for (int gg = 0; gg < GRP; gg++)
            if (g_counts[gg * KC + k] == 0.f) bad = true;
        float c = g_counts[b];
        denom_s = (c == 0.f) ? 1.f : c;
        bad_s = bad ? 1 : 0;
    }
    __syncthreads();
    emit_planes(g, k, b, &g_sums[b * DIM], denom_s, bad_s, out, true);
}

// ---------------- fused assign(fp16 3-term MMA) + sum, persistent ----------
__global__ void __launch_bounds__(THREADS, 1) fused_kernel(const float* __restrict__ patches) {
    extern __shared__ float sm[];
    uint32_t* Apk = (uint32_t*)sm;                 // [2][128][APW]
    uint32_t* Bpk = (uint32_t*)sm + 2 * APL2;      // [2][64][APW]
    float* acc = sm + ACC_F;
    float* cnt = sm + CNT_F;
    int*   lbl = (int*)(sm + LBL_F);
    float* c2s = sm + C2_F;

    const int tid = threadIdx.x;
    const int w = tid >> 5, lane = tid & 31;
    const int tg = lane >> 2, tq = lane & 3;
    const int mw = w >> 1;                 // 0..7: 16-row slab
    const int nh = w & 1;                  // 0..1: 32-col half
    const int g = blockIdx.y;

    for (int i = tid; i < KC * DIM; i += THREADS) acc[i] = 0.f;
    if (tid < KC) { cnt[tid] = 0.f; c2s[tid] = g_c2[g * KC + tid]; }
    __syncthreads();

    for (int t = 0; ; t++) {
        const int tile = blockIdx.x + CTAS_X * t;
        if (tile >= TILES_G) break;
        const int row0 = tile * TM;
        const int nvalid = min(TM, N_PATCH - row0);
        const float* abase = patches + (size_t)row0 * ROWSTRIDE + g * DIM;

        float ac1[4][4], ac2[4][4];
#pragma unroll
        for (int j = 0; j < 4; j++)
#pragma unroll
            for (int q = 0; q < 4; q++) { ac1[j][q] = 0.f; ac2[j][q] = 0.f; }

        // prefetch chunk 0: 128 rows x 32 cols = 1024 float4
        float4 apf[2];
#pragma unroll
        for (int it = 0; it < 2; it++) {
            int idx = tid + it * THREADS;
            int r = idx >> 3, c4 = idx & 7;
            apf[it] = make_float4(0.f, 0.f, 0.f, 0.f);
            if (r < nvalid)
                apf[it] = *(const float4*)(abase + (size_t)r * ROWSTRIDE + c4 * 4);
        }

        for (int kc = 0; kc < NCH; kc++) {
            __syncthreads();
            // store prefetched A as packed fp16 pairs, 2 planes
#pragma unroll
            for (int it = 0; it < 2; it++) {
                int idx = tid + it * THREADS;
                int r = idx >> 3, c4 = idx & 7;
                float4 v = apf[it];
                uint32_t h0,l0,h1,l1,h2,l2,h3,l3;
                split2h(v.x, h0, l0); split2h(v.y, h1, l1);
                split2h(v.z, h2, l2); split2h(v.w, h3, l3);
                uint32_t base = r * APW + 2 * c4;
                *(uint2*)&Apk[0 * APL2 + base] = make_uint2(pack2(h0, h1), pack2(h2, h3));
                *(uint2*)&Apk[1 * APL2 + base] = make_uint2(pack2(l0, l1), pack2(l2, l3));
            }
            // stage B planes: 2 x 64 x 16 pairs = 512 uint4
            {
                int idx = tid;
                if (idx < 512) {
                    int p = idx >> 8, e = idx & 255;
                    int n = e >> 2, q = e & 3;
                    uint4 v = *(const uint4*)&g_cbp[g][p][n][kc * 16 + q * 4];
                    *(uint4*)&Bpk[p * BPL2 + n * APW + q * 4] = v;
                }
            }
            __syncthreads();
            // prefetch next chunk (hidden under MMA)
            if (kc + 1 < NCH) {
                const int kn = (kc + 1) * 32;
#pragma unroll
                for (int it = 0; it < 2; it++) {
                    int idx = tid + it * THREADS;
                    int r = idx >> 3, c4 = idx & 7;
                    int col = kn + c4 * 4;
                    apf[it] = make_float4(0.f, 0.f, 0.f, 0.f);
                    if (r < nvalid && col < DIM)
                        apf[it] = *(const float4*)(abase + (size_t)r * ROWSTRIDE + col);
                }
            }
            // 2 k16-steps per chunk
#pragma unroll
            for (int s = 0; s < 2; s++) {
                const int ar = (mw * 16 + tg) * APW + 8 * s + tq;
                uint32_t ah[4], al[4];
#define LDAF(dst, P) \
                dst[0] = Apk[P * APL2 + ar]; \
                dst[1] = Apk[P * APL2 + ar + 8 * APW]; \
                dst[2] = Apk[P * APL2 + ar + 4]; \
                dst[3] = Apk[P * APL2 + ar + 8 * APW + 4];
                LDAF(ah, 0) LDAF(al, 1)
#undef LDAF
#pragma unroll
                for (int j = 0; j < 4; j++) {
                    const int nb = (nh * 32 + 8 * j + tg) * APW + 8 * s + tq;
                    uint32_t bh0 = Bpk[0 * BPL2 + nb], bh1 = Bpk[0 * BPL2 + nb + 4];
                    uint32_t bl0 = Bpk[1 * BPL2 + nb], bl1 = Bpk[1 * BPL2 + nb + 4];
                    mma_f16(ac2[j], al, bh0, bh1);   // l'h -> scaled acc
                    mma_f16(ac2[j], ah, bl0, bl1);   // hl' -> scaled acc
                    mma_f16(ac1[j], ah, bh0, bh1);   // hh  -> main acc
                }
            }
        }
        __syncthreads();

        // epilogue: combine accs -> Cs[128][65] (raw scores)
        float* Cs = sm;
#pragma unroll
        for (int j = 0; j < 4; j++) {
            int c0 = nh * 32 + j * 8 + 2 * tq;
            int rr = mw * 16 + tg;
            Cs[rr * 65 + c0]     = ac1[j][0] + LINV * ac2[j][0];
            Cs[rr * 65 + c0 + 1] = ac1[j][1] + LINV * ac2[j][1];
            Cs[(rr + 8) * 65 + c0]     = ac1[j][2] + LINV * ac2[j][2];
            Cs[(rr + 8) * 65 + c0 + 1] = ac1[j][3] + LINV * ac2[j][3];
        }
        __syncthreads();

        // argmax (first-max ties), labels in smem
        if (tid < TM && tid < nvalid) {
            const float* row = &Cs[tid * 65];
            float best = row[0] - c2s[0];
            int bi = 0;
#pragma unroll
            for (int k2 = 1; k2 < KC; k2++) {
                float v = row[k2] - c2s[k2];
                if (v > best) { best = v; bi = k2; }
            }
            lbl[tid] = bi;
        }
        __syncthreads();

        // accumulate: re-read tile rows (L2-hot) into smem accumulator
        const bool col_ok = (tid < DIM);
        for (int pb = 0; pb < nvalid; pb += 8) {
            int nu = min(8, nvalid - pb);
            int   l[8];
            float v0[8];
#pragma unroll
            for (int u = 0; u < 8; u++) {
                bool ok = (u < nu);
                int pp = ok ? (pb + u) : 0;
                l[u] = lbl[pp];
                v0[u] = (ok && col_ok) ? abase[(size_t)pp * ROWSTRIDE + tid] : 0.f;
            }
#pragma unroll
            for (int u = 0; u < 8; u++) {
                if (u < nu && col_ok) acc[l[u] * DIM + tid] += v0[u];
            }
        }
        if (tid < nvalid) atomicAdd(&cnt[lbl[tid]], 1.f);
        __syncthreads();
    }

    // flush accumulator + counts (once per persistent CTA)
    for (int i = tid * 4; i < KC * DIM; i += THREADS * 4) {
        float4 v = *(const float4*)&acc[i];
        float* dst = &g_sums[(size_t)g * KC * DIM + i];
        asm volatile("red.global.add.v4.f32 [%0], {%1, %2, %3, %4};"
                     :: "l"(dst), "f"(v.x), "f"(v.y), "f"(v.z), "f"(v.w)
                     : "memory");
    }
    if (tid < KC) atomicAdd(&g_counts[g * KC + tid], cnt[tid]);
}

// ---------------- launch ----------------
extern "C" void kernel_launch(void* const* d_in, const int* in_sizes, int n_in,
                              void* d_out, int out_size) {
    const float* patches = (const float*)d_in[0];
    const float* cinit   = (const float*)d_in[1];
    float* out = (float*)d_out;

    cudaFuncSetAttribute(fused_kernel, cudaFuncAttributeMaxDynamicSharedMemorySize, FUSED_SMEM);

    copy_init_kernel<<<(GRP * KC * DIM + 255) / 256, 256>>>(cinit);
    prep_kernel<<<GRP * KC, 128>>>();

    for (int e = 0; e < EPOCHS; e++) {
        fused_kernel<<<dim3(CTAS_X, GRP), THREADS, FUSED_SMEM>>>(patches);
        finalize_kernel<<<GRP * KC, 128>>>(e == EPOCHS - 1 ? out : nullptr);
    }
}

// round 13
// speedup vs baseline: 1.9167x; 1.0237x over previous
#include <cuda_runtime.h>
#include <cuda_fp16.h>
#include <stdint.h>

// ---------------- problem constants ----------------
#define N_PATCH   40000
#define GRP       4
#define DIM       400          // 16*5*5
#define KC        64
#define EPOCHS    10
#define ROWSTRIDE 1600         // GRP*DIM floats per patch row
#define TM        128          // patches per tile (MMA M)
#define KPADP     208          // K padded to 416 = 208 fp16-pairs
#define NCH       13           // chunks of 32 k (16 pairs)
#define TILES_G   313
#define CTAS_X    37           // persistent: 37*4 = 148 CTAs = 1 wave
#define THREADS   512
#define LSCALE    2048.0f      // low-plane scale 2^11
#define LINV      4.8828125e-4f

// fused-kernel smem layout
#define APW    20              // pair-slots per row (16 + 4 pad) in uint32
#define APL2   (128*APW)       // 2560 u32 per A plane
#define BPL2   (64*APW)        // 1280 u32 per B plane
#define STG_F  8320            // union: 2*APL2+2*BPL2=7680 staged OR Cs 128*65
#define ACC_F  STG_F
#define CNT_F  (ACC_F + KC*DIM)
#define LBL_F  (CNT_F + KC)
#define C2_F   (LBL_F + TM)
#define FUSED_F (C2_F + KC)            // 34176 floats
#define FUSED_SMEM (FUSED_F * 4)       // 136,704 B -> 1 CTA/SM

// ---------------- device state ----------------
__device__ float g_centroids[GRP * KC * DIM];
__device__ float g_c2[GRP * KC];
__device__ __align__(16) float g_sums[GRP * KC * DIM];
__device__ float g_counts[GRP * KC];
// centroid fp16-pair-packed planes (h, l'=l*2^11)
__device__ __align__(16) uint32_t g_cbp[GRP][2][KC][KPADP];

// ---------------- fp16 split helpers ----------------
__device__ __forceinline__ void split2h(float x, uint32_t& h, uint32_t& l) {
    __half hh = __float2half_rn(x);
    float r = x - __half2float(hh);
    __half ll = __float2half_rn(r * LSCALE);
    h = (uint32_t)__half_as_ushort(hh);
    l = (uint32_t)__half_as_ushort(ll);
}
__device__ __forceinline__ uint32_t pack2(uint32_t a, uint32_t b) {
    return a | (b << 16);
}
__device__ __forceinline__ void mma_f16(float* c, const uint32_t* a,
                                        uint32_t b0, uint32_t b1) {
    asm volatile(
        "mma.sync.aligned.m16n8k16.row.col.f32.f16.f16.f32 "
        "{%0,%1,%2,%3}, {%4,%5,%6,%7}, {%8,%9}, {%0,%1,%2,%3};"
        : "+f"(c[0]), "+f"(c[1]), "+f"(c[2]), "+f"(c[3])
        : "r"(a[0]), "r"(a[1]), "r"(a[2]), "r"(a[3]), "r"(b0), "r"(b1));
}
__device__ __forceinline__ void ldsm4(uint32_t* r, uint32_t saddr) {
    asm volatile("ldmatrix.sync.aligned.m8n8.x4.shared.b16 {%0,%1,%2,%3}, [%4];"
                 : "=r"(r[0]), "=r"(r[1]), "=r"(r[2]), "=r"(r[3]) : "r"(saddr));
}
__device__ __forceinline__ uint32_t s2u(const void* p) {
    uint32_t a;
    asm("{ .reg .u64 t; cvta.to.shared.u64 t, %1; cvt.u32.u64 %0, t; }"
        : "=r"(a) : "l"(p));
    return a;
}

// ---------------- small kernels ----------------
__global__ void copy_init_kernel(const float* __restrict__ cin) {
    int i = blockIdx.x * blockDim.x + threadIdx.x;
    if (i < GRP * KC * DIM) g_centroids[i] = cin[i];
}

__device__ __forceinline__ void emit_planes(int g, int k, int b, const float* src,
                                            float denom, int bad, float* out,
                                            bool writeback) {
    float s = 0.f;
    for (int pp = threadIdx.x; pp < KPADP; pp += 128) {
        int k0 = 2 * pp;
        float v0 = 0.f, v1 = 0.f;
        if (k0 < DIM) {
            v0 = bad ? 0.f : src[k0] / denom;
            if (writeback) {
                g_centroids[b * DIM + k0] = v0;
                if (out) out[b * DIM + k0] = v0;
                g_sums[b * DIM + k0] = 0.f;
            }
            s += v0 * v0;
        }
        if (k0 + 1 < DIM) {
            v1 = bad ? 0.f : src[k0 + 1] / denom;
            if (writeback) {
                g_centroids[b * DIM + k0 + 1] = v1;
                if (out) out[b * DIM + k0 + 1] = v1;
                g_sums[b * DIM + k0 + 1] = 0.f;
            }
            s += v1 * v1;
        }
        uint32_t h0, l0, h1, l1;
        split2h(v0, h0, l0);
        split2h(v1, h1, l1);
        g_cbp[g][0][k][pp] = pack2(h0, h1);
        g_cbp[g][1][k][pp] = pack2(l0, l1);
    }
#pragma unroll
    for (int o = 16; o; o >>= 1) s += __shfl_down_sync(0xffffffffu, s, o);
    __shared__ float ws[4];
    if ((threadIdx.x & 31) == 0) ws[threadIdx.x >> 5] = s;
    __syncthreads();
    if (threadIdx.x == 0) {
        g_c2[b] = 0.5f * (ws[0] + ws[1] + ws[2] + ws[3]);
        g_counts[b] = 0.f;
    }
}

__global__ void prep_kernel() {
    int b = blockIdx.x, g = b / KC, k = b % KC;
    for (int d = threadIdx.x; d < DIM; d += 128) g_sums[b * DIM + d] = 0.f;
    emit_planes(g, k, b, &g_centroids[b * DIM], 1.f, 0, nullptr, false);
}

__global__ void finalize_kernel(float* out) {
    int b = blockIdx.x, g = b / KC, k = b % KC;
    __shared__ float denom_s;
    __shared__ int bad_s;
    if (threadIdx.x == 0) {
        bool bad = false;
        for (int gg = 0; gg < GRP; gg++)
            if (g_counts[gg * KC + k] == 0.f) bad = true;
        float c = g_counts[b];
        denom_s = (c == 0.f) ? 1.f : c;
        bad_s = bad ? 1 : 0;
    }
    __syncthreads();
    emit_planes(g, k, b, &g_sums[b * DIM], denom_s, bad_s, out, true);
}

// ---------------- fused assign(fp16 3-term MMA, ldmatrix) + sum ------------
__global__ void __launch_bounds__(THREADS, 1) fused_kernel(const float* __restrict__ patches) {
    extern __shared__ float sm[];
    uint32_t* Apk = (uint32_t*)sm;                 // [2][128][APW]
    uint32_t* Bpk = (uint32_t*)sm + 2 * APL2;      // [2][64][APW]
    float* acc = sm + ACC_F;
    float* cnt = sm + CNT_F;
    int*   lbl = (int*)(sm + LBL_F);
    float* c2s = sm + C2_F;

    const int tid = threadIdx.x;
    const int w = tid >> 5, lane = tid & 31;
    const int tq = lane & 3;
    const int mw = w >> 1;                 // 0..7: 16-row slab
    const int nh = w & 1;                  // 0..1: 32-col half
    const int g = blockIdx.y;

    // ldmatrix lane geometry
    const int q8 = lane >> 3;              // quad 0..3
    const int r8 = lane & 7;               // row within matrix

    const uint32_t sb = s2u(sm);
    const uint32_t A_base = sb;                       // Apk in bytes
    const uint32_t B_base = sb + 2 * APL2 * 4;

    // A ldmatrix address (bytes), per plane p and step s:
    //   row = mw*16 + (q8&1)*8 + r8 ; pair = 8s + (q8>>1)*4
    const uint32_t a_row_off = ((mw * 16 + (q8 & 1) * 8 + r8) * APW + (q8 >> 1) * 4) * 4;
    // B ldmatrix address, per plane p, step s, j-pair jp:
    //   row n = nh*32 + jp*16 + (q8>>1)*8 + r8 ; pair = 8s + (q8&1)*4
    const uint32_t b_row_off0 = ((nh * 32 + (q8 >> 1) * 8 + r8) * APW + (q8 & 1) * 4) * 4;

    for (int i = tid; i < KC * DIM; i += THREADS) acc[i] = 0.f;
    if (tid < KC) { cnt[tid] = 0.f; c2s[tid] = g_c2[g * KC + tid]; }
    __syncthreads();

    for (int t = 0; ; t++) {
        const int tile = blockIdx.x + CTAS_X * t;
        if (tile >= TILES_G) break;
        const int row0 = tile * TM;
        const int nvalid = min(TM, N_PATCH - row0);
        const float* abase = patches + (size_t)row0 * ROWSTRIDE + g * DIM;

        float ac1[4][4], ac2[4][4];
#pragma unroll
        for (int j = 0; j < 4; j++)
#pragma unroll
            for (int q = 0; q < 4; q++) { ac1[j][q] = 0.f; ac2[j][q] = 0.f; }

        // prefetch chunk 0
        float4 apf[2];
#pragma unroll
        for (int it = 0; it < 2; it++) {
            int idx = tid + it * THREADS;
            int r = idx >> 3, c4 = idx & 7;
            apf[it] = make_float4(0.f, 0.f, 0.f, 0.f);
            if (r < nvalid)
                apf[it] = *(const float4*)(abase + (size_t)r * ROWSTRIDE + c4 * 4);
        }

        for (int kc = 0; kc < NCH; kc++) {
            __syncthreads();
            // store prefetched A as packed fp16 pairs, 2 planes
#pragma unroll
            for (int it = 0; it < 2; it++) {
                int idx = tid + it * THREADS;
                int r = idx >> 3, c4 = idx & 7;
                float4 v = apf[it];
                uint32_t h0,l0,h1,l1,h2,l2,h3,l3;
                split2h(v.x, h0, l0); split2h(v.y, h1, l1);
                split2h(v.z, h2, l2); split2h(v.w, h3, l3);
                uint32_t base = r * APW + 2 * c4;
                *(uint2*)&Apk[0 * APL2 + base] = make_uint2(pack2(h0, h1), pack2(h2, h3));
                *(uint2*)&Apk[1 * APL2 + base] = make_uint2(pack2(l0, l1), pack2(l2, l3));
            }
            // stage B planes: 2 x 64 x 16 pairs = 512 uint4
            if (tid < 512) {
                int p = tid >> 8, e = tid & 255;
                int n = e >> 2, q = e & 3;
                uint4 v = *(const uint4*)&g_cbp[g][p][n][kc * 16 + q * 4];
                *(uint4*)&Bpk[p * BPL2 + n * APW + q * 4] = v;
            }
            __syncthreads();
            // prefetch next chunk (hidden under MMA)
            if (kc + 1 < NCH) {
                const int kn = (kc + 1) * 32;
#pragma unroll
                for (int it = 0; it < 2; it++) {
                    int idx = tid + it * THREADS;
                    int r = idx >> 3, c4 = idx & 7;
                    int col = kn + c4 * 4;
                    apf[it] = make_float4(0.f, 0.f, 0.f, 0.f);
                    if (r < nvalid && col < DIM)
                        apf[it] = *(const float4*)(abase + (size_t)r * ROWSTRIDE + col);
                }
            }
            // 2 k16-steps per chunk, ldmatrix fragment loads
#pragma unroll
            for (int s = 0; s < 2; s++) {
                const uint32_t soff = (8 * s) * 4;
                uint32_t ah[4], al[4];
                ldsm4(ah, A_base + 0 * APL2 * 4 + a_row_off + soff);
                ldsm4(al, A_base + 1 * APL2 * 4 + a_row_off + soff);
#pragma unroll
                for (int jp = 0; jp < 2; jp++) {
                    const uint32_t joff = (jp * 16 * APW) * 4;
                    uint32_t bh[4], bl[4];
                    ldsm4(bh, B_base + 0 * BPL2 * 4 + b_row_off0 + joff + soff);
                    ldsm4(bl, B_base + 1 * BPL2 * 4 + b_row_off0 + joff + soff);
                    const int j0 = 2 * jp;
                    mma_f16(ac2[j0], al, bh[0], bh[1]);
                    mma_f16(ac2[j0], ah, bl[0], bl[1]);
                    mma_f16(ac1[j0], ah, bh[0], bh[1]);
                    mma_f16(ac2[j0 + 1], al, bh[2], bh[3]);
                    mma_f16(ac2[j0 + 1], ah, bl[2], bl[3]);
                    mma_f16(ac1[j0 + 1], ah, bh[2], bh[3]);
                }
            }
        }
        __syncthreads();

        // epilogue: combine accs -> Cs[128][65]
        float* Cs = sm;
        {
            const int tg = lane >> 2;
#pragma unroll
            for (int j = 0; j < 4; j++) {
                int c0 = nh * 32 + j * 8 + 2 * tq;
                int rr = mw * 16 + tg;
                Cs[rr * 65 + c0]     = ac1[j][0] + LINV * ac2[j][0];
                Cs[rr * 65 + c0 + 1] = ac1[j][1] + LINV * ac2[j][1];
                Cs[(rr + 8) * 65 + c0]     = ac1[j][2] + LINV * ac2[j][2];
                Cs[(rr + 8) * 65 + c0 + 1] = ac1[j][3] + LINV * ac2[j][3];
            }
        }
        __syncthreads();

        // parallel argmax: 4 threads/row, 16 cols each, shfl merge.
        // First-max ties preserved: segment scan is first-max; merges prefer
        // lower index on equal values.
        {
            int row = tid >> 2, seg = tid & 3;
            const float* r = &Cs[row * 65];
            int c0 = seg * 16;
            float best = r[c0] - c2s[c0];
            int bi = c0;
#pragma unroll
            for (int k2 = 1; k2 < 16; k2++) {
                float v = r[c0 + k2] - c2s[c0 + k2];
                if (v > best) { best = v; bi = c0 + k2; }
            }
#pragma unroll
            for (int o = 1; o < 4; o <<= 1) {
                float vo = __shfl_xor_sync(0xffffffffu, best, o);
                int   io = __shfl_xor_sync(0xffffffffu, bi, o);
                if (vo > best || (vo == best && io < bi)) { best = vo; bi = io; }
            }
            if (seg == 0 && row < nvalid) lbl[row] = bi;
        }
        __syncthreads();

        // accumulate: re-read tile rows (L2-hot) into smem accumulator
        const bool col_ok = (tid < DIM);
        for (int pb = 0; pb < nvalid; pb += 8) {
            int nu = min(8, nvalid - pb);
            int   l[8];
            float v0[8];
#pragma unroll
            for (int u = 0; u < 8; u++) {
                bool ok = (u < nu);
                int pp = ok ? (pb + u) : 0;
                l[u] = lbl[pp];
                v0[u] = (ok && col_ok) ? abase[(size_t)pp * ROWSTRIDE + tid] : 0.f;
            }
#pragma unroll
            for (int u = 0; u < 8; u++) {
                if (u < nu && col_ok) acc[l[u] * DIM + tid] += v0[u];
            }
        }
        if (tid < nvalid) atomicAdd(&cnt[lbl[tid]], 1.f);
        __syncthreads();
    }

    // flush accumulator + counts (once per persistent CTA)
    for (int i = tid * 4; i < KC * DIM; i += THREADS * 4) {
        float4 v = *(const float4*)&acc[i];
        float* dst = &g_sums[(size_t)g * KC * DIM + i];
        asm volatile("red.global.add.v4.f32 [%0], {%1, %2, %3, %4};"
                     :: "l"(dst), "f"(v.x), "f"(v.y), "f"(v.z), "f"(v.w)
                     : "memory");
    }
    if (tid < KC) atomicAdd(&g_counts[g * KC + tid], cnt[tid]);
}

// ---------------- launch ----------------
extern "C" void kernel_launch(void* const* d_in, const int* in_sizes, int n_in,
                              void* d_out, int out_size) {
    const float* patches = (const float*)d_in[0];
    const float* cinit   = (const float*)d_in[1];
    float* out = (float*)d_out;

    cudaFuncSetAttribute(fused_kernel, cudaFuncAttributeMaxDynamicSharedMemorySize, FUSED_SMEM);

    copy_init_kernel<<<(GRP * KC * DIM + 255) / 256, 256>>>(cinit);
    prep_kernel<<<GRP * KC, 128>>>();

    for (int e = 0; e < EPOCHS; e++) {
        fused_kernel<<<dim3(CTAS_X, GRP), THREADS, FUSED_SMEM>>>(patches);
        finalize_kernel<<<GRP * KC, 128>>>(e == EPOCHS - 1 ? out : nullptr);
    }
}

// round 14
// speedup vs baseline: 1.9574x; 1.0213x over previous
#include <cuda_runtime.h>
#include <cuda_fp16.h>
#include <stdint.h>

// ---------------- problem constants ----------------
#define N_PATCH   40000
#define GRP       4
#define DIM       400          // 16*5*5
#define KC        64
#define EPOCHS    10
#define ROWSTRIDE 1600         // GRP*DIM floats per patch row
#define TM        128          // patches per tile (MMA M)
#define KPADP     208          // K padded to 416 = 208 fp16-pairs
#define NCH       13           // chunks of 32 k (16 pairs)
#define TILES_G   313
#define CTAS_X    37           // persistent: 37*4 = 148 CTAs = 1 wave
#define THREADS   512
#define LSCALE    2048.0f      // low-plane scale 2^11
#define LINV      4.8828125e-4f

// fused-kernel smem layout (double-buffered staging)
#define APW    20              // pair-slots per row (16 + 4 pad) in uint32
#define APL2   (128*APW)       // 2560 u32 per A plane
#define BPL2   (64*APW)        // 1280 u32 per B plane
#define ABUFS  (2*APL2)        // one A buffer (2 planes)
#define BBUFS  (2*BPL2)        // one B buffer (2 planes)
#define STG_F  (2*ABUFS + 2*BBUFS)     // 15360 u32 (>= Cs 128*65=8320)
#define ACC_F  STG_F
#define CNT_F  (ACC_F + KC*DIM)        // 40960
#define LBL_F  (CNT_F + KC)
#define C2_F   (LBL_F + TM)
#define FUSED_F (C2_F + KC)            // 41216 floats
#define FUSED_SMEM (FUSED_F * 4)       // 164,864 B -> 1 CTA/SM

// ---------------- device state ----------------
__device__ float g_centroids[GRP * KC * DIM];
__device__ float g_c2[GRP * KC];
__device__ __align__(16) float g_sums[GRP * KC * DIM];
__device__ float g_counts[GRP * KC];
// centroid fp16-pair-packed planes (h, l'=l*2^11)
__device__ __align__(16) uint32_t g_cbp[GRP][2][KC][KPADP];

// ---------------- fp16 split helpers ----------------
__device__ __forceinline__ void split2h(float x, uint32_t& h, uint32_t& l) {
    __half hh = __float2half_rn(x);
    float r = x - __half2float(hh);
    __half ll = __float2half_rn(r * LSCALE);
    h = (uint32_t)__half_as_ushort(hh);
    l = (uint32_t)__half_as_ushort(ll);
}
__device__ __forceinline__ uint32_t pack2(uint32_t a, uint32_t b) {
    return a | (b << 16);
}
__device__ __forceinline__ void mma_f16(float* c, const uint32_t* a,
                                        uint32_t b0, uint32_t b1) {
    asm volatile(
        "mma.sync.aligned.m16n8k16.row.col.f32.f16.f16.f32 "
        "{%0,%1,%2,%3}, {%4,%5,%6,%7}, {%8,%9}, {%0,%1,%2,%3};"
        : "+f"(c[0]), "+f"(c[1]), "+f"(c[2]), "+f"(c[3])
        : "r"(a[0]), "r"(a[1]), "r"(a[2]), "r"(a[3]), "r"(b0), "r"(b1));
}
__device__ __forceinline__ void ldsm4(uint32_t* r, uint32_t saddr) {
    asm volatile("ldmatrix.sync.aligned.m8n8.x4.shared.b16 {%0,%1,%2,%3}, [%4];"
                 : "=r"(r[0]), "=r"(r[1]), "=r"(r[2]), "=r"(r[3]) : "r"(saddr));
}
__device__ __forceinline__ uint32_t s2u(const void* p) {
    uint32_t a;
    asm("{ .reg .u64 t; cvta.to.shared.u64 t, %1; cvt.u32.u64 %0, t; }"
        : "=r"(a) : "l"(p));
    return a;
}

// ---------------- small kernels ----------------
__global__ void copy_init_kernel(const float* __restrict__ cin) {
    int i = blockIdx.x * blockDim.x + threadIdx.x;
    if (i < GRP * KC * DIM) g_centroids[i] = cin[i];
}

__device__ __forceinline__ void emit_planes(int g, int k, int b, const float* src,
                                            float denom, int bad, float* out,
                                            bool writeback) {
    float s = 0.f;
    for (int pp = threadIdx.x; pp < KPADP; pp += 128) {
        int k0 = 2 * pp;
        float v0 = 0.f, v1 = 0.f;
        if (k0 < DIM) {
            v0 = bad ? 0.f : src[k0] / denom;
            if (writeback) {
                g_centroids[b * DIM + k0] = v0;
                if (out) out[b * DIM + k0] = v0;
                g_sums[b * DIM + k0] = 0.f;
            }
            s += v0 * v0;
        }
        if (k0 + 1 < DIM) {
            v1 = bad ? 0.f : src[k0 + 1] / denom;
            if (writeback) {
                g_centroids[b * DIM + k0 + 1] = v1;
                if (out) out[b * DIM + k0 + 1] = v1;
                g_sums[b * DIM + k0 + 1] = 0.f;
            }
            s += v1 * v1;
        }
        uint32_t h0, l0, h1, l1;
        split2h(v0, h0, l0);
        split2h(v1, h1, l1);
        g_cbp[g][0][k][pp] = pack2(h0, h1);
        g_cbp[g][1][k][pp] = pack2(l0, l1);
    }
#pragma unroll
    for (int o = 16; o; o >>= 1) s += __shfl_down_sync(0xffffffffu, s, o);
    __shared__ float ws[4];
    if ((threadIdx.x & 31) == 0) ws[threadIdx.x >> 5] = s;
    __syncthreads();
    if (threadIdx.x == 0) {
        g_c2[b] = 0.5f * (ws[0] + ws[1] + ws[2] + ws[3]);
        g_counts[b] = 0.f;
    }
}

__global__ void prep_kernel() {
    int b = blockIdx.x, g = b / KC, k = b % KC;
    for (int d = threadIdx.x; d < DIM; d += 128) g_sums[b * DIM + d] = 0.f;
    emit_planes(g, k, b, &g_centroids[b * DIM], 1.f, 0, nullptr, false);
}

__global__ void finalize_kernel(float* out) {
    int b = blockIdx.x, g = b / KC, k = b % KC;
    __shared__ float denom_s;
    __shared__ int bad_s;
    if (threadIdx.x == 0) {
        bool bad = false;
        for (int gg = 0; gg < GRP; gg++)
            if (g_counts[gg * KC + k] == 0.f) bad = true;
        float c = g_counts[b];
        denom_s = (c == 0.f) ? 1.f : c;
        bad_s = bad ? 1 : 0;
    }
    __syncthreads();
    emit_planes(g, k, b, &g_sums[b * DIM], denom_s, bad_s, out, true);
}

// ---------- fused assign(fp16 3-term MMA, ldmatrix, dbl-buffer) + sum ------
__global__ void __launch_bounds__(THREADS, 1) fused_kernel(const float* __restrict__ patches) {
    extern __shared__ float sm[];
    uint32_t* Apk = (uint32_t*)sm;                    // [2buf][2pl][128][APW]
    uint32_t* Bpk = (uint32_t*)sm + 2 * ABUFS;        // [2buf][2pl][64][APW]
    float* acc = sm + ACC_F;
    float* cnt = sm + CNT_F;
    int*   lbl = (int*)(sm + LBL_F);
    float* c2s = sm + C2_F;

    const int tid = threadIdx.x;
    const int w = tid >> 5, lane = tid & 31;
    const int tq = lane & 3;
    const int mw = w >> 1;                 // 0..7: 16-row slab
    const int nh = w & 1;                  // 0..1: 32-col half
    const int g = blockIdx.y;

    // ldmatrix lane geometry
    const int q8 = lane >> 3;
    const int r8 = lane & 7;

    const uint32_t sb = s2u(sm);
    const uint32_t A_base = sb;
    const uint32_t B_base = sb + 2 * ABUFS * 4;

    const uint32_t a_row_off = ((mw * 16 + (q8 & 1) * 8 + r8) * APW + (q8 >> 1) * 4) * 4;
    const uint32_t b_row_off0 = ((nh * 32 + (q8 >> 1) * 8 + r8) * APW + (q8 & 1) * 4) * 4;

    for (int i = tid; i < KC * DIM; i += THREADS) acc[i] = 0.f;
    if (tid < KC) { cnt[tid] = 0.f; c2s[tid] = g_c2[g * KC + tid]; }
    __syncthreads();

    for (int t = 0; ; t++) {
        const int tile = blockIdx.x + CTAS_X * t;
        if (tile >= TILES_G) break;
        const int row0 = tile * TM;
        const int nvalid = min(TM, N_PATCH - row0);
        const float* abase = patches + (size_t)row0 * ROWSTRIDE + g * DIM;

        float ac1[4][4], ac2[4][4];
#pragma unroll
        for (int j = 0; j < 4; j++)
#pragma unroll
            for (int q = 0; q < 4; q++) { ac1[j][q] = 0.f; ac2[j][q] = 0.f; }

        // prefetch chunk 0 into registers
        float4 apf[2];
#pragma unroll
        for (int it = 0; it < 2; it++) {
            int idx = tid + it * THREADS;
            int r = idx >> 3, c4 = idx & 7;
            apf[it] = make_float4(0.f, 0.f, 0.f, 0.f);
            if (r < nvalid)
                apf[it] = *(const float4*)(abase + (size_t)r * ROWSTRIDE + c4 * 4);
        }

        for (int kc = 0; kc < NCH; kc++) {
            const int buf = kc & 1;
            uint32_t* Ab = Apk + buf * ABUFS;
            uint32_t* Bb = Bpk + buf * BBUFS;
            // store prefetched A as packed fp16 pairs, 2 planes
#pragma unroll
            for (int it = 0; it < 2; it++) {
                int idx = tid + it * THREADS;
                int r = idx >> 3, c4 = idx & 7;
                float4 v = apf[it];
                uint32_t h0,l0,h1,l1,h2,l2,h3,l3;
                split2h(v.x, h0, l0); split2h(v.y, h1, l1);
                split2h(v.z, h2, l2); split2h(v.w, h3, l3);
                uint32_t base = r * APW + 2 * c4;
                *(uint2*)&Ab[0 * APL2 + base] = make_uint2(pack2(h0, h1), pack2(h2, h3));
                *(uint2*)&Ab[1 * APL2 + base] = make_uint2(pack2(l0, l1), pack2(l2, l3));
            }
            // stage B chunk: 2 x 64 x 16 pairs = 512 uint4
            if (tid < 512) {
                int p = tid >> 8, e = tid & 255;
                int n = e >> 2, q = e & 3;
                uint4 v = *(const uint4*)&g_cbp[g][p][n][kc * 16 + q * 4];
                *(uint4*)&Bb[p * BPL2 + n * APW + q * 4] = v;
            }
            __syncthreads();   // single barrier: stores of chunk kc visible
            // prefetch next chunk (LDG hidden under MMA below)
            if (kc + 1 < NCH) {
                const int kn = (kc + 1) * 32;
#pragma unroll
                for (int it = 0; it < 2; it++) {
                    int idx = tid + it * THREADS;
                    int r = idx >> 3, c4 = idx & 7;
                    int col = kn + c4 * 4;
                    apf[it] = make_float4(0.f, 0.f, 0.f, 0.f);
                    if (r < nvalid && col < DIM)
                        apf[it] = *(const float4*)(abase + (size_t)r * ROWSTRIDE + col);
                }
            }
            // MMA on buf (2 k16-steps), ldmatrix fragment loads
            const uint32_t Abase = A_base + buf * ABUFS * 4;
            const uint32_t Bbase = B_base + buf * BBUFS * 4;
#pragma unroll
            for (int s = 0; s < 2; s++) {
                const uint32_t soff = (8 * s) * 4;
                uint32_t ah[4], al[4];
                ldsm4(ah, Abase + 0 * APL2 * 4 + a_row_off + soff);
                ldsm4(al, Abase + 1 * APL2 * 4 + a_row_off + soff);
#pragma unroll
                for (int jp = 0; jp < 2; jp++) {
                    const uint32_t joff = (jp * 16 * APW) * 4;
                    uint32_t bh[4], bl[4];
                    ldsm4(bh, Bbase + 0 * BPL2 * 4 + b_row_off0 + joff + soff);
                    ldsm4(bl, Bbase + 1 * BPL2 * 4 + b_row_off0 + joff + soff);
                    const int j0 = 2 * jp;
                    mma_f16(ac2[j0], al, bh[0], bh[1]);
                    mma_f16(ac2[j0], ah, bl[0], bl[1]);
                    mma_f16(ac1[j0], ah, bh[0], bh[1]);
                    mma_f16(ac2[j0 + 1], al, bh[2], bh[3]);
                    mma_f16(ac2[j0 + 1], ah, bl[2], bl[3]);
                    mma_f16(ac1[j0 + 1], ah, bh[2], bh[3]);
                }
            }
        }
        __syncthreads();   // all MMA fragment reads done before Cs overwrite

        // epilogue: combine accs -> Cs[128][65]
        float* Cs = sm;
        {
            const int tg = lane >> 2;
#pragma unroll
            for (int j = 0; j < 4; j++) {
                int c0 = nh * 32 + j * 8 + 2 * tq;
                int rr = mw * 16 + tg;
                Cs[rr * 65 + c0]     = ac1[j][0] + LINV * ac2[j][0];
                Cs[rr * 65 + c0 + 1] = ac1[j][1] + LINV * ac2[j][1];
                Cs[(rr + 8) * 65 + c0]     = ac1[j][2] + LINV * ac2[j][2];
                Cs[(rr + 8) * 65 + c0 + 1] = ac1[j][3] + LINV * ac2[j][3];
            }
        }
        __syncthreads();

        // parallel argmax: 4 threads/row, 16 cols each, shfl merge (first-max)
        {
            int row = tid >> 2, seg = tid & 3;
            const float* r = &Cs[row * 65];
            int c0 = seg * 16;
            float best = r[c0] - c2s[c0];
            int bi = c0;
#pragma unroll
            for (int k2 = 1; k2 < 16; k2++) {
                float v = r[c0 + k2] - c2s[c0 + k2];
                if (v > best) { best = v; bi = c0 + k2; }
            }
#pragma unroll
            for (int o = 1; o < 4; o <<= 1) {
                float vo = __shfl_xor_sync(0xffffffffu, best, o);
                int   io = __shfl_xor_sync(0xffffffffu, bi, o);
                if (vo > best || (vo == best && io < bi)) { best = vo; bi = io; }
            }
            if (seg == 0 && row < nvalid) lbl[row] = bi;
        }
        __syncthreads();

        // accumulate: re-read tile rows (L2-hot) into smem accumulator
        const bool col_ok = (tid < DIM);
        for (int pb = 0; pb < nvalid; pb += 8) {
            int nu = min(8, nvalid - pb);
            int   l[8];
            float v0[8];
#pragma unroll
            for (int u = 0; u < 8; u++) {
                bool ok = (u < nu);
                int pp = ok ? (pb + u) : 0;
                l[u] = lbl[pp];
                v0[u] = (ok && col_ok) ? abase[(size_t)pp * ROWSTRIDE + tid] : 0.f;
            }
#pragma unroll
            for (int u = 0; u < 8; u++) {
                if (u < nu && col_ok) acc[l[u] * DIM + tid] += v0[u];
            }
        }
        if (tid < nvalid) atomicAdd(&cnt[lbl[tid]], 1.f);
        __syncthreads();
    }

    // flush accumulator + counts (once per persistent CTA)
    for (int i = tid * 4; i < KC * DIM; i += THREADS * 4) {
        float4 v = *(const float4*)&acc[i];
        float* dst = &g_sums[(size_t)g * KC * DIM + i];
        asm volatile("red.global.add.v4.f32 [%0], {%1, %2, %3, %4};"
                     :: "l"(dst), "f"(v.x), "f"(v.y), "f"(v.z), "f"(v.w)
                     : "memory");
    }
    if (tid < KC) atomicAdd(&g_counts[g * KC + tid], cnt[tid]);
}

// ---------------- launch ----------------
extern "C" void kernel_launch(void* const* d_in, const int* in_sizes, int n_in,
                              void* d_out, int out_size) {
    const float* patches = (const float*)d_in[0];
    const float* cinit   = (const float*)d_in[1];
    float* out = (float*)d_out;

    cudaFuncSetAttribute(fused_kernel, cudaFuncAttributeMaxDynamicSharedMemorySize, FUSED_SMEM);

    copy_init_kernel<<<(GRP * KC * DIM + 255) / 256, 256>>>(cinit);
    prep_kernel<<<GRP * KC, 128>>>();

    for (int e = 0; e < EPOCHS; e++) {
        fused_kernel<<<dim3(CTAS_X, GRP), THREADS, FUSED_SMEM>>>(patches);
        finalize_kernel<<<GRP * KC, 128>>>(e == EPOCHS - 1 ? out : nullptr);
    }
}